// round 10
// baseline (speedup 1.0000x reference)
#include <cuda_runtime.h>
#include <cstdint>

// Problem constants
#define N_NODES 16384
#define KNBR    32
#define DIN     256
#define DOUT    256
#define DCAT    512
#define NROWS   (N_NODES * KNBR)   // 524288

// ---------------------------------------------------------------------------
// Scratch (static device globals — no runtime allocation)
// ---------------------------------------------------------------------------
__device__ float g_Q[N_NODES * DOUT];          // 16 MB
__device__ float g_KV[268435456];              // NROWS*DCAT = 1 GB: per row [keys(256) | values(256)]
__device__ float g_rowsum[NROWS];              // 2 MB
__device__ float g_ctx[N_NODES * DOUT];        // 16 MB
__device__ float g_ob[N_NODES * DCAT];         // 32 MB  output = [self_out | neigh_out]
__device__ float g_gate[N_NODES * DCAT];       // 32 MB
__device__ float g_Wkv[DCAT * DIN];
__device__ float g_bkv[DCAT];
__device__ float g_psum[128 * DCAT];
__device__ float g_psq[128 * DCAT];
__device__ float g_mean[DCAT];
__device__ float g_rstd[DCAT];

// ---------------------------------------------------------------------------
// Packed fp32x2 helpers (Blackwell FFMA2 path: 2x throughput vs 3-reg FFMA)
// ---------------------------------------------------------------------------
__device__ __forceinline__ unsigned long long pack2(float x) {
    unsigned long long r;
    asm("mov.b64 %0, {%1, %1};" : "=l"(r) : "r"(__float_as_uint(x)));
    return r;
}

__device__ __forceinline__ void ffma2(unsigned long long& c,
                                      unsigned long long a,
                                      unsigned long long b) {
    asm("fma.rn.f32x2 %0, %1, %2, %0;" : "+l"(c) : "l"(a), "l"(b));
}

// ---------------------------------------------------------------------------
// Tiled SGEMM: C[m][n] = sum_k A[m][k] * W[n][k] + bias[n]   (A: MxK, W: NxK)
// BM=BN=128, BK=16, 256 threads, 8x8 per thread, fp32x2 accumulators.
// Requires M,N multiples of 128 and K multiple of 16 (true for all calls).
// ---------------------------------------------------------------------------
template <bool RELU>
__global__ void __launch_bounds__(256, 2)
sgemm_kernel(const float* __restrict__ A, const float* __restrict__ W,
             const float* __restrict__ bias, float* __restrict__ C,
             int K, int ldc)
{
    __shared__ float As[16][128];
    __shared__ float Bs[16][128];

    const int    tid = threadIdx.x;
    const size_t bm  = (size_t)blockIdx.y * 128;
    const int    bn  = blockIdx.x * 128;
    const int    tx  = tid & 15, ty = tid >> 4;
    const int    m0  = ty * 8,   n0 = tx * 8;
    const int    lr  = tid >> 2;          // 0..63
    const int    lk  = (tid & 3) * 4;     // 0,4,8,12

    unsigned long long acc[8][4];
#pragma unroll
    for (int i = 0; i < 8; i++)
#pragma unroll
        for (int j = 0; j < 4; j++) acc[i][j] = 0ull;

    for (int k0 = 0; k0 < K; k0 += 16) {
        float4 a0 = *(const float4*)(A + (bm + lr) * (size_t)K + k0 + lk);
        float4 a1 = *(const float4*)(A + (bm + lr + 64) * (size_t)K + k0 + lk);
        float4 w0 = *(const float4*)(W + (size_t)(bn + lr) * K + k0 + lk);
        float4 w1 = *(const float4*)(W + (size_t)(bn + lr + 64) * K + k0 + lk);
        __syncthreads();
        As[lk + 0][lr]      = a0.x; As[lk + 1][lr]      = a0.y;
        As[lk + 2][lr]      = a0.z; As[lk + 3][lr]      = a0.w;
        As[lk + 0][lr + 64] = a1.x; As[lk + 1][lr + 64] = a1.y;
        As[lk + 2][lr + 64] = a1.z; As[lk + 3][lr + 64] = a1.w;
        Bs[lk + 0][lr]      = w0.x; Bs[lk + 1][lr]      = w0.y;
        Bs[lk + 2][lr]      = w0.z; Bs[lk + 3][lr]      = w0.w;
        Bs[lk + 0][lr + 64] = w1.x; Bs[lk + 1][lr + 64] = w1.y;
        Bs[lk + 2][lr + 64] = w1.z; Bs[lk + 3][lr + 64] = w1.w;
        __syncthreads();

#pragma unroll
        for (int kk = 0; kk < 16; kk++) {
            float4 av0 = *(const float4*)&As[kk][m0];
            float4 av1 = *(const float4*)&As[kk][m0 + 4];
            ulonglong2 bq0 = *(const ulonglong2*)&Bs[kk][n0];
            ulonglong2 bq1 = *(const ulonglong2*)&Bs[kk][n0 + 4];
            const unsigned long long bp0 = bq0.x, bp1 = bq0.y;
            const unsigned long long bp2 = bq1.x, bp3 = bq1.y;
            float am[8] = {av0.x, av0.y, av0.z, av0.w, av1.x, av1.y, av1.z, av1.w};
#pragma unroll
            for (int i = 0; i < 8; i++) {
                unsigned long long ap = pack2(am[i]);
                ffma2(acc[i][0], ap, bp0);
                ffma2(acc[i][1], ap, bp1);
                ffma2(acc[i][2], ap, bp2);
                ffma2(acc[i][3], ap, bp3);
            }
        }
    }

    float bcol[8];
#pragma unroll
    for (int j = 0; j < 8; j++) bcol[j] = bias[bn + n0 + j];
#pragma unroll
    for (int i = 0; i < 8; i++) {
        float* crow = C + (bm + m0 + i) * (size_t)ldc + bn + n0;
#pragma unroll
        for (int j = 0; j < 4; j++) {
            float lo = __uint_as_float((unsigned)(acc[i][j] & 0xffffffffull)) + bcol[2 * j];
            float hi = __uint_as_float((unsigned)(acc[i][j] >> 32)) + bcol[2 * j + 1];
            if (RELU) { lo = fmaxf(lo, 0.f); hi = fmaxf(hi, 0.f); }
            crow[2 * j]     = lo;
            crow[2 * j + 1] = hi;
        }
    }
}

// ---------------------------------------------------------------------------
// Pack Wkv = [Wk ; Wv] (512 x 256), bkv = [bk ; bv]
// ---------------------------------------------------------------------------
__global__ void pack_wkv_kernel(const float* __restrict__ Wk, const float* __restrict__ bk,
                                const float* __restrict__ Wv, const float* __restrict__ bv,
                                float* __restrict__ Wkv, float* __restrict__ bkv)
{
    const int nrow = blockIdx.x;
    const int t    = threadIdx.x;
    const float* src = (nrow < DOUT) ? (Wk + (size_t)nrow * DIN)
                                     : (Wv + (size_t)(nrow - DOUT) * DIN);
    Wkv[(size_t)nrow * DIN + t] = src[t];
    if (t == 0) bkv[nrow] = (nrow < DOUT) ? bk[nrow] : bv[nrow - DOUT];
}

// ---------------------------------------------------------------------------
// Row sums of neighbor_inputs (for the exact ==0 padding mask)
// 8 rows per CTA, one warp per row.
// ---------------------------------------------------------------------------
__global__ void __launch_bounds__(256)
rowsum_kernel(const float* __restrict__ X, float* __restrict__ rs)
{
    const int row  = blockIdx.x * 8 + (threadIdx.x >> 5);
    const int lane = threadIdx.x & 31;
    const float4* p = (const float4*)(X + (size_t)row * DIN) + lane * 2;
    float4 v0 = p[0], v1 = p[1];
    float s = v0.x + v0.y + v0.z + v0.w + v1.x + v1.y + v1.z + v1.w;
#pragma unroll
    for (int o = 16; o; o >>= 1) s += __shfl_xor_sync(0xffffffffu, s, o);
    if (lane == 0) rs[row] = s;
}

// ---------------------------------------------------------------------------
// Fused attention: energies -> mask -> softmax -> context, one node per CTA
// ---------------------------------------------------------------------------
__global__ void __launch_bounds__(256)
attn_kernel(const float* __restrict__ Q, const float* __restrict__ KV,
            const float* __restrict__ rowsum, float* __restrict__ ctx)
{
    __shared__ float qs[256];
    __shared__ float es[32];
    __shared__ float att[32];
    const int n    = blockIdx.x;
    const int t    = threadIdx.x;
    const int lane = t & 31, w = t >> 5;

    qs[t] = Q[(size_t)n * DOUT + t];
    __syncthreads();

    // energies: 8 warps x 4 neighbors each
#pragma unroll
    for (int i = 0; i < 4; i++) {
        const int k = w * 4 + i;
        const float* kr = KV + ((size_t)n * KNBR + k) * DCAT + lane * 8;
        float4 k0 = *(const float4*)kr;
        float4 k1 = *(const float4*)(kr + 4);
        const float* qp = qs + lane * 8;
        float p = k0.x * qp[0] + k0.y * qp[1] + k0.z * qp[2] + k0.w * qp[3]
                + k1.x * qp[4] + k1.y * qp[5] + k1.z * qp[6] + k1.w * qp[7];
#pragma unroll
        for (int o = 16; o; o >>= 1) p += __shfl_xor_sync(0xffffffffu, p, o);
        if (lane == 0) es[k] = p;
    }
    __syncthreads();

    // softmax over K=32 (warp 0), masked positions forced to 1e-12 pre-softmax
    if (t < 32) {
        float e = es[t];
        if (rowsum[(size_t)n * KNBR + t] == 0.0f) e = 1e-12f;
        float m = e;
#pragma unroll
        for (int o = 16; o; o >>= 1) m = fmaxf(m, __shfl_xor_sync(0xffffffffu, m, o));
        float ex = expf(e - m);
        float s = ex;
#pragma unroll
        for (int o = 16; o; o >>= 1) s += __shfl_xor_sync(0xffffffffu, s, o);
        att[t] = ex / s;
    }
    __syncthreads();

    // context[d] = sum_k att[k] * values[n,k,d]   (values = KV cols 256..511)
    const float* vb = KV + (size_t)n * KNBR * DCAT + DOUT + t;
    float c = 0.f;
#pragma unroll
    for (int k = 0; k < KNBR; k++) c = fmaf(att[k], vb[(size_t)k * DCAT], c);
    ctx[(size_t)n * DOUT + t] = c;
}

// ---------------------------------------------------------------------------
// BatchNorm statistics: two-phase deterministic reduction
// ---------------------------------------------------------------------------
__global__ void __launch_bounds__(256)
bn_partial_kernel(const float* __restrict__ ob, float* __restrict__ psum,
                  float* __restrict__ psq)
{
    const int b = blockIdx.x, t = threadIdx.x;  // 128 blocks x 128 rows each
    float s0 = 0, s1 = 0, q0 = 0, q1 = 0;
    for (int r = 0; r < 128; r++) {
        const float* row = ob + ((size_t)b * 128 + r) * DCAT;
        float x0 = row[t], x1 = row[t + 256];
        s0 += x0; q0 += x0 * x0;
        s1 += x1; q1 += x1 * x1;
    }
    psum[b * DCAT + t]       = s0;
    psum[b * DCAT + t + 256] = s1;
    psq[b * DCAT + t]        = q0;
    psq[b * DCAT + t + 256]  = q1;
}

__global__ void bn_final_kernel(const float* __restrict__ psum, const float* __restrict__ psq,
                                float* __restrict__ mean, float* __restrict__ rstd)
{
    const int c = blockIdx.x * 256 + threadIdx.x;
    float s = 0, q = 0;
    for (int b = 0; b < 128; b++) { s += psum[b * DCAT + c]; q += psq[b * DCAT + c]; }
    float m = s / (float)N_NODES;
    float v = q / (float)N_NODES - m * m;   // biased variance (ddof=0)
    mean[c] = m;
    rstd[c] = rsqrtf(v + 1e-5f);
}

// ---------------------------------------------------------------------------
// Final elementwise: out = gate * relu(gamma*(output-mean)*rstd + beta)
// ---------------------------------------------------------------------------
__global__ void __launch_bounds__(256)
final_kernel(const float* __restrict__ ob, const float* __restrict__ gate,
             const float* __restrict__ mean, const float* __restrict__ rstd,
             const float* __restrict__ gamma, const float* __restrict__ beta,
             float* __restrict__ out)
{
    const size_t i = (size_t)blockIdx.x * 256 + threadIdx.x;   // float4 index
    const int    c = ((int)(i & 127)) * 4;
    float4 x = ((const float4*)ob)[i];
    float4 g = ((const float4*)gate)[i];
    float4 r;
    r.x = g.x * fmaxf(gamma[c + 0] * (x.x - mean[c + 0]) * rstd[c + 0] + beta[c + 0], 0.f);
    r.y = g.y * fmaxf(gamma[c + 1] * (x.y - mean[c + 1]) * rstd[c + 1] + beta[c + 1], 0.f);
    r.z = g.z * fmaxf(gamma[c + 2] * (x.z - mean[c + 2]) * rstd[c + 2] + beta[c + 2], 0.f);
    r.w = g.w * fmaxf(gamma[c + 3] * (x.w - mean[c + 3]) * rstd[c + 3] + beta[c + 3], 0.f);
    ((float4*)out)[i] = r;
}

// ---------------------------------------------------------------------------
// Launch
// ---------------------------------------------------------------------------
extern "C" void kernel_launch(void* const* d_in, const int* in_sizes, int n_in,
                              void* d_out, int out_size)
{
    const float* input = (const float*)d_in[0];
    const float* nbr   = (const float*)d_in[1];
    const float* Wq    = (const float*)d_in[2];
    const float* bq    = (const float*)d_in[3];
    const float* Wk    = (const float*)d_in[4];
    const float* bk    = (const float*)d_in[5];
    const float* Wv    = (const float*)d_in[6];
    const float* bv    = (const float*)d_in[7];
    const float* Wno   = (const float*)d_in[8];
    const float* bno   = (const float*)d_in[9];
    const float* Wio   = (const float*)d_in[10];
    const float* bio   = (const float*)d_in[11];
    const float* Wg    = (const float*)d_in[12];
    const float* bg    = (const float*)d_in[13];
    const float* gamma = (const float*)d_in[14];
    const float* beta  = (const float*)d_in[15];
    float* out = (float*)d_out;

    float *Qp, *KVp, *rsp, *ctxp, *obp, *gatep, *Wkvp, *bkvp, *psump, *psqp, *meanp, *rstdp;
    cudaGetSymbolAddress((void**)&Qp,    g_Q);
    cudaGetSymbolAddress((void**)&KVp,   g_KV);
    cudaGetSymbolAddress((void**)&rsp,   g_rowsum);
    cudaGetSymbolAddress((void**)&ctxp,  g_ctx);
    cudaGetSymbolAddress((void**)&obp,   g_ob);
    cudaGetSymbolAddress((void**)&gatep, g_gate);
    cudaGetSymbolAddress((void**)&Wkvp,  g_Wkv);
    cudaGetSymbolAddress((void**)&bkvp,  g_bkv);
    cudaGetSymbolAddress((void**)&psump, g_psum);
    cudaGetSymbolAddress((void**)&psqp,  g_psq);
    cudaGetSymbolAddress((void**)&meanp, g_mean);
    cudaGetSymbolAddress((void**)&rstdp, g_rstd);

    // Independent prep
    pack_wkv_kernel<<<DCAT, 256>>>(Wk, bk, Wv, bv, Wkvp, bkvp);
    rowsum_kernel<<<NROWS / 8, 256>>>(nbr, rsp);

    // queries = input @ Wq^T + bq
    sgemm_kernel<false><<<dim3(DOUT / 128, N_NODES / 128), 256>>>(input, Wq, bq, Qp, DIN, DOUT);
    // self_out = input @ Wio^T + bio  -> output[:, 0:256]
    sgemm_kernel<false><<<dim3(DOUT / 128, N_NODES / 128), 256>>>(input, Wio, bio, obp, DIN, DCAT);

    // keys|values = neighbor_inputs @ [Wk;Wv]^T + [bk;bv]   (the heavy GEMM)
    sgemm_kernel<false><<<dim3(DCAT / 128, NROWS / 128), 256>>>(nbr, Wkvp, bkvp, KVp, DIN, DCAT);

    // attention: energies -> mask -> softmax -> context
    attn_kernel<<<N_NODES, 256>>>(Qp, KVp, rsp, ctxp);

    // neigh_out = context @ Wno^T + bno -> output[:, 256:512]
    sgemm_kernel<false><<<dim3(DOUT / 128, N_NODES / 128), 256>>>(ctxp, Wno, bno, obp + 256, DOUT, DCAT);

    // gate = relu(output @ Wg^T + bg)
    sgemm_kernel<true><<<dim3(DCAT / 128, N_NODES / 128), 256>>>(obp, Wg, bg, gatep, DCAT, DCAT);

    // BatchNorm statistics (deterministic two-phase) + final elementwise
    bn_partial_kernel<<<128, 256>>>(obp, psump, psqp);
    bn_final_kernel<<<2, 256>>>(psump, psqp, meanp, rstdp);
    final_kernel<<<(N_NODES * DCAT / 4) / 256, 256>>>(obp, gatep, meanp, rstdp, gamma, beta, out);
}

// round 13
// speedup vs baseline: 3.2533x; 3.2533x over previous
#include <cuda_runtime.h>
#include <cstdint>

// Problem constants
#define N_NODES 16384
#define KNBR    32
#define DIN     256
#define DOUT    256
#define DCAT    512
#define NROWS   (N_NODES * KNBR)   // 524288

// ---------------------------------------------------------------------------
// Arch gating: tcgen05 exists only under arch-SPECIFIC (sm_103a) compilation.
// The plain compute_103 PTX pass compiles the FFMA fallback body instead.
// ---------------------------------------------------------------------------
#if defined(__CUDA_ARCH__) && \
    (defined(__CUDA_ARCH_FEAT_SM103_ALL) || defined(__CUDA_ARCH_FEAT_SM100_ALL) || \
     (defined(__CUDA_ARCH_SPECIFIC__) && (__CUDA_ARCH_SPECIFIC__ >= 1000)))
#define HAS_TC 1
#else
#define HAS_TC 0
#endif

// ---------------------------------------------------------------------------
// Scratch (static device globals — no runtime allocation)
// ---------------------------------------------------------------------------
__device__ float g_Q[N_NODES * DOUT];
__device__ float g_KV[268435456];          // NROWS*DCAT: per row [keys(256)|values(256)]
__device__ float g_rowsum[NROWS];
__device__ float g_ctx[N_NODES * DOUT];
__device__ float g_ob[N_NODES * DCAT];
__device__ float g_gate[N_NODES * DCAT];
__device__ float g_Wkv[DCAT * DIN];        // packed + tf32-rounded [Wk;Wv]
__device__ float g_bkv[DCAT];
__device__ float g_Wq_r[DOUT * DIN];
__device__ float g_Wio_r[DOUT * DIN];
__device__ float g_Wno_r[DOUT * DOUT];
__device__ float g_Wg_r[DCAT * DCAT];
__device__ float g_psum[128 * DCAT];
__device__ float g_psq[128 * DCAT];
__device__ float g_mean[DCAT];
__device__ float g_rstd[DCAT];

// ---------------------------------------------------------------------------
// PTX helpers (arch-neutral)
// ---------------------------------------------------------------------------
__device__ __forceinline__ uint32_t smem_u32(const void* p) {
    uint32_t a;
    asm("{ .reg .u64 t; cvta.to.shared.u64 t, %1; cvt.u32.u64 %0, t; }" : "=r"(a) : "l"(p));
    return a;
}
__device__ __forceinline__ uint32_t rna_tf32(float f) {
    uint32_t r;
    asm("cvt.rna.tf32.f32 %0, %1;" : "=r"(r) : "f"(f));
    return r;
}
__device__ __forceinline__ uint32_t sw128(uint32_t off) { return off ^ ((off >> 3) & 0x70); }

#if HAS_TC
// ---------------------------------------------------------------------------
// tcgen05 helpers (compiled only for sm_10xa)
// ---------------------------------------------------------------------------
__device__ __forceinline__ uint32_t elect_one() {
    uint32_t p;
    asm volatile("{ .reg .pred P; elect.sync _|P, 0xFFFFFFFF; selp.b32 %0, 1, 0, P; }" : "=r"(p));
    return p;
}

#define TCGEN05_ALLOC(a, n) \
    asm volatile("tcgen05.alloc.cta_group::1.sync.aligned.shared::cta.b32 [%0], %1;" \
                 :: "r"(a), "r"(n) : "memory")
#define TCGEN05_DEALLOC(t, n) \
    asm volatile("tcgen05.dealloc.cta_group::1.sync.aligned.b32 %0, %1;" :: "r"(t), "r"(n))
#define TCGEN05_RELINQ() \
    asm volatile("tcgen05.relinquish_alloc_permit.cta_group::1.sync.aligned;")
#define TCGEN05_COMMIT(m) \
    asm volatile("tcgen05.commit.cta_group::1.mbarrier::arrive::one.shared::cluster.b64 [%0];" \
                 :: "r"(m) : "memory")
#define TCGEN05_FENCE_AFTER()  asm volatile("tcgen05.fence::after_thread_sync;" ::: "memory")
#define TCGEN05_FENCE_BEFORE() asm volatile("tcgen05.fence::before_thread_sync;" ::: "memory")
#define TCGEN05_WAIT_LD()      asm volatile("tcgen05.wait::ld.sync.aligned;" ::: "memory")
#define MBARRIER_INIT(m, c) \
    asm volatile("mbarrier.init.shared.b64 [%0], %1;" :: "r"(m), "r"(c) : "memory")

#define MBARRIER_WAIT_PARITY(mbar_smem_addr, phase_parity) do { \
    uint32_t _mbar = (uint32_t)(mbar_smem_addr); \
    uint32_t _parity = (uint32_t)(phase_parity); \
    uint32_t _done; \
    asm volatile( \
        "{\n\t" \
        ".reg .pred p;\n\t" \
        "mbarrier.try_wait.parity.acquire.cta.shared::cta.b64 p, [%1], %2;\n\t" \
        "selp.b32 %0, 1, 0, p;\n\t" \
        "}" \
        : "=r"(_done) : "r"(_mbar), "r"(_parity) : "memory"); \
    if (!_done) { \
        asm volatile( \
            "{\n\t" \
            ".reg .pred P1;\n\t" \
            "WAIT_LOOP_%=:\n\t" \
            "mbarrier.try_wait.parity.acquire.cta.shared::cta.b64 P1, [%0], %1, 0x989680;\n\t" \
            "@P1 bra.uni WAIT_DONE_%=;\n\t" \
            "bra.uni WAIT_LOOP_%=;\n\t" \
            "WAIT_DONE_%=:\n\t" \
            "}" \
            :: "r"(_mbar), "r"(_parity) : "memory"); \
    } \
} while (0)

#define TCGEN05_LD_32X32B_X32(r, tmem_addr) \
    asm volatile( \
        "tcgen05.ld.sync.aligned.32x32b.x32.b32 " \
        "{%0, %1, %2, %3, %4, %5, %6, %7, " \
        " %8, %9, %10, %11, %12, %13, %14, %15, " \
        " %16, %17, %18, %19, %20, %21, %22, %23, " \
        " %24, %25, %26, %27, %28, %29, %30, %31}, [%32];" \
        : "=r"((r)[0]),  "=r"((r)[1]),  "=r"((r)[2]),  "=r"((r)[3]), \
          "=r"((r)[4]),  "=r"((r)[5]),  "=r"((r)[6]),  "=r"((r)[7]), \
          "=r"((r)[8]),  "=r"((r)[9]),  "=r"((r)[10]), "=r"((r)[11]), \
          "=r"((r)[12]), "=r"((r)[13]), "=r"((r)[14]), "=r"((r)[15]), \
          "=r"((r)[16]), "=r"((r)[17]), "=r"((r)[18]), "=r"((r)[19]), \
          "=r"((r)[20]), "=r"((r)[21]), "=r"((r)[22]), "=r"((r)[23]), \
          "=r"((r)[24]), "=r"((r)[25]), "=r"((r)[26]), "=r"((r)[27]), \
          "=r"((r)[28]), "=r"((r)[29]), "=r"((r)[30]), "=r"((r)[31]) \
        : "r"(tmem_addr))

// SW128 K-major SMEM descriptor (LBO=1, SBO=64, version=1, layout=SW128)
__device__ __forceinline__ uint64_t sw128_desc(uint32_t addr) {
    constexpr uint64_t base = (2ull << 61) | (1ull << 46) | (64ull << 32) | (1ull << 16);
    return base | ((uint64_t)(addr >> 4) & 0x3FFFull);
}

// tcgen05 tf32 SS MMA: D[M=128, N=256] += A(smem desc) * B(smem desc)^T
__device__ __forceinline__ void mma_tf32_ss(uint32_t d, uint64_t ad, uint64_t bd,
                                            uint32_t idesc, uint32_t acc) {
    asm volatile(
        "{\n\t"
        ".reg .pred p;\n\t"
        "setp.ne.u32 p, %4, 0;\n\t"
        "tcgen05.mma.cta_group::1.kind::tf32 [%0], %1, %2, %3, p;\n\t"
        "}"
        :: "r"(d), "l"(ad), "l"(bd), "r"(idesc), "r"(acc) : "memory");
}

// idesc: dtype F32 (1<<4), atype TF32 (2<<7), btype TF32 (2<<10), N/8<<17, M/16<<24
// (cross-checked against the validated bf16 constant 0x8080490: same fields,
//  format code 1(BF16) -> 2(TF32), N=256, M=128)
static constexpr uint32_t IDESC_TF32_128x256 =
    (1u << 4) | (2u << 7) | (2u << 10) | (32u << 17) | (8u << 24);
#endif  // HAS_TC

// ---------------------------------------------------------------------------
// Generic GEMM: C[m][n] = A[m][:] . W[n][:] + bias[n]
// M-tile = 128 rows (gridDim.x tiles), 128 threads. NT = N-tiles of 256.
// K = NC*32. A is fp32 (tf32-rounded during staging); W pre-rounded.
// sm_103a body: tcgen05 tf32 SS, double-buffered staging, D in TMEM.
// generic body:  tiled FFMA fallback (never executes on the GB300 — the
//                exact-match sm_103a cubin is always preferred).
// ---------------------------------------------------------------------------
template <int NT, int NC, bool RELU>
__global__ void __launch_bounds__(128, 1)
tc_gemm_kernel(const float* __restrict__ A, const float* __restrict__ W,
               const float* __restrict__ bias, float* __restrict__ C, int ldc)
{
    constexpr int NTOT = NT * 256;
    constexpr int K    = NC * 32;

#if HAS_TC
    constexpr int STAGE = (128 + NTOT) * 128;   // bytes per buffer (A tile + B tile)

    extern __shared__ __align__(1024) char smem[];
    const uint32_t sb   = smem_u32(smem);
    const int      tid  = threadIdx.x;
    const int      wid  = tid >> 5, lane = tid & 31;
    const size_t   bm   = (size_t)blockIdx.x * 128;

    // smem: [0]=tmem ptr, [8],[16]=mbarriers, buffers at +1024
    if (wid == 0) TCGEN05_ALLOC(sb, 512);
    if (tid == 0) { MBARRIER_INIT(sb + 8, 1); MBARRIER_INIT(sb + 16, 1); }
    __syncthreads();
    uint32_t tb;
    asm volatile("ld.shared.b32 %0, [%1];" : "=r"(tb) : "r"(sb));

    const uint32_t aBase0 = sb + 1024;
    const uint32_t bBase0 = aBase0 + 128 * 128;

    int ph0 = 0, ph1 = 0;

    for (int c = 0; c < NC; c++) {
        const int      buf = c & 1;
        const uint32_t aB  = aBase0 + buf * STAGE;
        const uint32_t bB  = bBase0 + buf * STAGE;

        // Guard buffer reuse: wait for MMAs of chunk c-2 on this buffer
        if (c >= 2) {
            if (buf == 0) { MBARRIER_WAIT_PARITY(sb + 8,  ph0); ph0 ^= 1; }
            else          { MBARRIER_WAIT_PARITY(sb + 16, ph1); ph1 ^= 1; }
        }

        const int k0 = c * 32;

        // Stage A chunk [128 x 32 fp32], rounding to tf32 (rna)
        for (int idx = tid; idx < 128 * 8; idx += 128) {
            const int r = idx >> 3, q = idx & 7;
            float4 v = *(const float4*)(A + (bm + r) * (size_t)K + k0 + q * 4);
            uint32_t x = rna_tf32(v.x), y = rna_tf32(v.y), z = rna_tf32(v.z), w = rna_tf32(v.w);
            uint32_t dst = aB + sw128((uint32_t)(r * 128 + q * 16));
            asm volatile("st.shared.v4.b32 [%0], {%1,%2,%3,%4};"
                         :: "r"(dst), "r"(x), "r"(y), "r"(z), "r"(w) : "memory");
        }
        // Stage B chunk [NTOT x 32 fp32] (pre-rounded weights)
        for (int idx = tid; idx < NTOT * 8; idx += 128) {
            const int r = idx >> 3, q = idx & 7;
            float4 v = *(const float4*)(W + (size_t)r * K + k0 + q * 4);
            uint32_t dst = bB + sw128((uint32_t)(r * 128 + q * 16));
            asm volatile("st.shared.v4.b32 [%0], {%1,%2,%3,%4};"
                         :: "r"(dst),
                            "r"(__float_as_uint(v.x)), "r"(__float_as_uint(v.y)),
                            "r"(__float_as_uint(v.z)), "r"(__float_as_uint(v.w)) : "memory");
        }
        TCGEN05_FENCE_BEFORE();
        __syncthreads();

        // Issue 4 K-steps (K=8 each) per chunk, per N-half; commit to buffer mbar
        if (wid == 0) {
            TCGEN05_FENCE_AFTER();
            if (elect_one()) {
                const uint64_t ad  = sw128_desc(aB);
                const uint64_t bd0 = sw128_desc(bB);
                const uint64_t bd1 = sw128_desc(bB + 256 * 128);
#pragma unroll
                for (int s = 0; s < 4; s++) {
                    const uint32_t acc = (c > 0 || s > 0) ? 1u : 0u;
                    mma_tf32_ss(tb,       ad + 2 * s, bd0 + 2 * s, IDESC_TF32_128x256, acc);
                    if (NT == 2)
                        mma_tf32_ss(tb + 256, ad + 2 * s, bd1 + 2 * s, IDESC_TF32_128x256, acc);
                }
                TCGEN05_COMMIT(sb + 8 + buf * 8);
            }
        }
    }

    // Drain both buffers' final commits
    MBARRIER_WAIT_PARITY(sb + 8,  ph0);
    MBARRIER_WAIT_PARITY(sb + 16, ph1);
    TCGEN05_FENCE_AFTER();

    // Epilogue: each warp reads its 32-row TMEM subpartition; row = bm + wid*32 + lane
    const size_t row  = bm + (size_t)wid * 32 + lane;
    float* const crow = C + row * (size_t)ldc;
#pragma unroll
    for (int g = 0; g < NT * 8; g++) {
        uint32_t r[32];
        TCGEN05_LD_32X32B_X32(r, tb + g * 32);
        TCGEN05_WAIT_LD();
        const int c0 = g * 32;
#pragma unroll
        for (int j = 0; j < 32; j += 4) {
            float4 o;
            o.x = __uint_as_float(r[j + 0]) + bias[c0 + j + 0];
            o.y = __uint_as_float(r[j + 1]) + bias[c0 + j + 1];
            o.z = __uint_as_float(r[j + 2]) + bias[c0 + j + 2];
            o.w = __uint_as_float(r[j + 3]) + bias[c0 + j + 3];
            if (RELU) {
                o.x = fmaxf(o.x, 0.f); o.y = fmaxf(o.y, 0.f);
                o.z = fmaxf(o.z, 0.f); o.w = fmaxf(o.w, 0.f);
            }
            *(float4*)(crow + c0 + j) = o;
        }
    }
    TCGEN05_FENCE_BEFORE();

    __syncthreads();
    if (wid == 0) { TCGEN05_RELINQ(); TCGEN05_DEALLOC(tb, 512); }

#else  // ----- generic fallback (correctness-only; never runs on sm_103a) ----
    extern __shared__ __align__(1024) char smem[];
    float (*As)[128] = (float (*)[128])smem;                   // [16][128]
    float (*Bs)[64]  = (float (*)[64])(smem + 16 * 128 * 4);   // [16][64]
    const int    tid = threadIdx.x;
    const size_t bm  = (size_t)blockIdx.x * 128;
    const int    ty  = tid >> 3, tx = tid & 7;   // 16 x 8 thread grid
    const int    m0  = ty * 8,  n0 = tx * 8;

    for (int nb = 0; nb < NTOT; nb += 64) {
        float acc[8][8];
#pragma unroll
        for (int i = 0; i < 8; i++)
#pragma unroll
            for (int j = 0; j < 8; j++) acc[i][j] = 0.f;

        for (int k0 = 0; k0 < K; k0 += 16) {
            __syncthreads();
            for (int idx = tid; idx < 16 * 128; idx += 128) {
                const int m = idx & 127, kk = idx >> 7;
                As[kk][m] = A[(bm + m) * (size_t)K + k0 + kk];
            }
            for (int idx = tid; idx < 16 * 64; idx += 128) {
                const int n = idx & 63, kk = idx >> 6;
                Bs[kk][n] = W[(size_t)(nb + n) * K + k0 + kk];
            }
            __syncthreads();
#pragma unroll
            for (int kk = 0; kk < 16; kk++)
#pragma unroll
                for (int i = 0; i < 8; i++) {
                    const float a = As[kk][m0 + i];
#pragma unroll
                    for (int j = 0; j < 8; j++) acc[i][j] = fmaf(a, Bs[kk][n0 + j], acc[i][j]);
                }
        }
#pragma unroll
        for (int i = 0; i < 8; i++)
#pragma unroll
            for (int j = 0; j < 8; j++) {
                float o = acc[i][j] + bias[nb + n0 + j];
                if (RELU) o = fmaxf(o, 0.f);
                C[(bm + m0 + i) * (size_t)ldc + nb + n0 + j] = o;
            }
    }
#endif
}

// ---------------------------------------------------------------------------
// Weight pre-rounding to tf32 (rna)
// ---------------------------------------------------------------------------
__global__ void round_tf32_kernel(const float* __restrict__ src, float* __restrict__ dst, int n)
{
    const int i = blockIdx.x * 256 + threadIdx.x;
    if (i < n) dst[i] = __uint_as_float(rna_tf32(src[i]));
}

// Pack Wkv = [Wk ; Wv] (512 x 256) with tf32 rounding; bkv = [bk ; bv]
__global__ void pack_wkv_kernel(const float* __restrict__ Wk, const float* __restrict__ bk,
                                const float* __restrict__ Wv, const float* __restrict__ bv,
                                float* __restrict__ Wkv, float* __restrict__ bkv)
{
    const int nrow = blockIdx.x;
    const int t    = threadIdx.x;
    const float* src = (nrow < DOUT) ? (Wk + (size_t)nrow * DIN)
                                     : (Wv + (size_t)(nrow - DOUT) * DIN);
    Wkv[(size_t)nrow * DIN + t] = __uint_as_float(rna_tf32(src[t]));
    if (t == 0) bkv[nrow] = (nrow < DOUT) ? bk[nrow] : bv[nrow - DOUT];
}

// ---------------------------------------------------------------------------
// Row sums of neighbor_inputs (exact fp32, for the ==0 padding mask)
// ---------------------------------------------------------------------------
__global__ void __launch_bounds__(256)
rowsum_kernel(const float* __restrict__ X, float* __restrict__ rs)
{
    const int row  = blockIdx.x * 8 + (threadIdx.x >> 5);
    const int lane = threadIdx.x & 31;
    const float4* p = (const float4*)(X + (size_t)row * DIN) + lane * 2;
    float4 v0 = p[0], v1 = p[1];
    float s = v0.x + v0.y + v0.z + v0.w + v1.x + v1.y + v1.z + v1.w;
#pragma unroll
    for (int o = 16; o; o >>= 1) s += __shfl_xor_sync(0xffffffffu, s, o);
    if (lane == 0) rs[row] = s;
}

// ---------------------------------------------------------------------------
// Fused attention: energies -> mask -> softmax -> context, one node per CTA
// ---------------------------------------------------------------------------
__global__ void __launch_bounds__(256)
attn_kernel(const float* __restrict__ Q, const float* __restrict__ KV,
            const float* __restrict__ rowsum, float* __restrict__ ctx)
{
    __shared__ float qs[256];
    __shared__ float es[32];
    __shared__ float att[32];
    const int n    = blockIdx.x;
    const int t    = threadIdx.x;
    const int lane = t & 31, w = t >> 5;

    qs[t] = Q[(size_t)n * DOUT + t];
    __syncthreads();

#pragma unroll
    for (int i = 0; i < 4; i++) {
        const int k = w * 4 + i;
        const float* kr = KV + ((size_t)n * KNBR + k) * DCAT + lane * 8;
        float4 k0 = *(const float4*)kr;
        float4 k1 = *(const float4*)(kr + 4);
        const float* qp = qs + lane * 8;
        float p = k0.x * qp[0] + k0.y * qp[1] + k0.z * qp[2] + k0.w * qp[3]
                + k1.x * qp[4] + k1.y * qp[5] + k1.z * qp[6] + k1.w * qp[7];
#pragma unroll
        for (int o = 16; o; o >>= 1) p += __shfl_xor_sync(0xffffffffu, p, o);
        if (lane == 0) es[k] = p;
    }
    __syncthreads();

    if (t < 32) {
        float e = es[t];
        if (rowsum[(size_t)n * KNBR + t] == 0.0f) e = 1e-12f;
        float m = e;
#pragma unroll
        for (int o = 16; o; o >>= 1) m = fmaxf(m, __shfl_xor_sync(0xffffffffu, m, o));
        float ex = expf(e - m);
        float s = ex;
#pragma unroll
        for (int o = 16; o; o >>= 1) s += __shfl_xor_sync(0xffffffffu, s, o);
        att[t] = ex / s;
    }
    __syncthreads();

    const float* vb = KV + (size_t)n * KNBR * DCAT + DOUT + t;
    float c = 0.f;
#pragma unroll
    for (int k = 0; k < KNBR; k++) c = fmaf(att[k], vb[(size_t)k * DCAT], c);
    ctx[(size_t)n * DOUT + t] = c;
}

// ---------------------------------------------------------------------------
// BatchNorm statistics + final elementwise
// ---------------------------------------------------------------------------
__global__ void __launch_bounds__(256)
bn_partial_kernel(const float* __restrict__ ob, float* __restrict__ psum,
                  float* __restrict__ psq)
{
    const int b = blockIdx.x, t = threadIdx.x;
    float s0 = 0, s1 = 0, q0 = 0, q1 = 0;
    for (int r = 0; r < 128; r++) {
        const float* row = ob + ((size_t)b * 128 + r) * DCAT;
        float x0 = row[t], x1 = row[t + 256];
        s0 += x0; q0 += x0 * x0;
        s1 += x1; q1 += x1 * x1;
    }
    psum[b * DCAT + t]       = s0;
    psum[b * DCAT + t + 256] = s1;
    psq[b * DCAT + t]        = q0;
    psq[b * DCAT + t + 256]  = q1;
}

__global__ void bn_final_kernel(const float* __restrict__ psum, const float* __restrict__ psq,
                                float* __restrict__ mean, float* __restrict__ rstd)
{
    const int c = blockIdx.x * 256 + threadIdx.x;
    float s = 0, q = 0;
    for (int b = 0; b < 128; b++) { s += psum[b * DCAT + c]; q += psq[b * DCAT + c]; }
    float m = s / (float)N_NODES;
    float v = q / (float)N_NODES - m * m;
    mean[c] = m;
    rstd[c] = rsqrtf(v + 1e-5f);
}

__global__ void __launch_bounds__(256)
final_kernel(const float* __restrict__ ob, const float* __restrict__ gate,
             const float* __restrict__ mean, const float* __restrict__ rstd,
             const float* __restrict__ gamma, const float* __restrict__ beta,
             float* __restrict__ out)
{
    const size_t i = (size_t)blockIdx.x * 256 + threadIdx.x;
    const int    c = ((int)(i & 127)) * 4;
    float4 x = ((const float4*)ob)[i];
    float4 g = ((const float4*)gate)[i];
    float4 r;
    r.x = g.x * fmaxf(gamma[c + 0] * (x.x - mean[c + 0]) * rstd[c + 0] + beta[c + 0], 0.f);
    r.y = g.y * fmaxf(gamma[c + 1] * (x.y - mean[c + 1]) * rstd[c + 1] + beta[c + 1], 0.f);
    r.z = g.z * fmaxf(gamma[c + 2] * (x.z - mean[c + 2]) * rstd[c + 2] + beta[c + 2], 0.f);
    r.w = g.w * fmaxf(gamma[c + 3] * (x.w - mean[c + 3]) * rstd[c + 3] + beta[c + 3], 0.f);
    ((float4*)out)[i] = r;
}

// ---------------------------------------------------------------------------
// Launch
// ---------------------------------------------------------------------------
extern "C" void kernel_launch(void* const* d_in, const int* in_sizes, int n_in,
                              void* d_out, int out_size)
{
    const float* input = (const float*)d_in[0];
    const float* nbr   = (const float*)d_in[1];
    const float* Wq    = (const float*)d_in[2];
    const float* bq    = (const float*)d_in[3];
    const float* Wk    = (const float*)d_in[4];
    const float* bk    = (const float*)d_in[5];
    const float* Wv    = (const float*)d_in[6];
    const float* bv    = (const float*)d_in[7];
    const float* Wno   = (const float*)d_in[8];
    const float* bno   = (const float*)d_in[9];
    const float* Wio   = (const float*)d_in[10];
    const float* bio   = (const float*)d_in[11];
    const float* Wg    = (const float*)d_in[12];
    const float* bg    = (const float*)d_in[13];
    const float* gamma = (const float*)d_in[14];
    const float* beta  = (const float*)d_in[15];
    float* out = (float*)d_out;

    float *Qp, *KVp, *rsp, *ctxp, *obp, *gatep, *Wkvp, *bkvp;
    float *Wqr, *Wior, *Wnor, *Wgr, *psump, *psqp, *meanp, *rstdp;
    cudaGetSymbolAddress((void**)&Qp,    g_Q);
    cudaGetSymbolAddress((void**)&KVp,   g_KV);
    cudaGetSymbolAddress((void**)&rsp,   g_rowsum);
    cudaGetSymbolAddress((void**)&ctxp,  g_ctx);
    cudaGetSymbolAddress((void**)&obp,   g_ob);
    cudaGetSymbolAddress((void**)&gatep, g_gate);
    cudaGetSymbolAddress((void**)&Wkvp,  g_Wkv);
    cudaGetSymbolAddress((void**)&bkvp,  g_bkv);
    cudaGetSymbolAddress((void**)&Wqr,   g_Wq_r);
    cudaGetSymbolAddress((void**)&Wior,  g_Wio_r);
    cudaGetSymbolAddress((void**)&Wnor,  g_Wno_r);
    cudaGetSymbolAddress((void**)&Wgr,   g_Wg_r);
    cudaGetSymbolAddress((void**)&psump, g_psum);
    cudaGetSymbolAddress((void**)&psqp,  g_psq);
    cudaGetSymbolAddress((void**)&meanp, g_mean);
    cudaGetSymbolAddress((void**)&rstdp, g_rstd);

    // Dynamic SMEM sizes: 1024 header + 2 buffers of (128+NTOT)*128 bytes
    const int SMEM1 = 1024 + 2 * (128 + 256) * 128;   //  99328
    const int SMEM2 = 1024 + 2 * (128 + 512) * 128;   // 164864
    cudaFuncSetAttribute(tc_gemm_kernel<1, 8,  false>, cudaFuncAttributeMaxDynamicSharedMemorySize, SMEM1);
    cudaFuncSetAttribute(tc_gemm_kernel<2, 8,  false>, cudaFuncAttributeMaxDynamicSharedMemorySize, SMEM2);
    cudaFuncSetAttribute(tc_gemm_kernel<2, 16, true>,  cudaFuncAttributeMaxDynamicSharedMemorySize, SMEM2);

    // Weight prep (tf32 rounding) + mask rowsums
    round_tf32_kernel<<<(DOUT * DIN + 255) / 256, 256>>>(Wq,  Wqr,  DOUT * DIN);
    round_tf32_kernel<<<(DOUT * DIN + 255) / 256, 256>>>(Wio, Wior, DOUT * DIN);
    round_tf32_kernel<<<(DOUT * DOUT + 255) / 256, 256>>>(Wno, Wnor, DOUT * DOUT);
    round_tf32_kernel<<<(DCAT * DCAT + 255) / 256, 256>>>(Wg,  Wgr,  DCAT * DCAT);
    pack_wkv_kernel<<<DCAT, 256>>>(Wk, bk, Wv, bv, Wkvp, bkvp);
    rowsum_kernel<<<NROWS / 8, 256>>>(nbr, rsp);

    // queries = input @ Wq^T + bq
    tc_gemm_kernel<1, 8, false><<<N_NODES / 128, 128, SMEM1>>>(input, Wqr, bq, Qp, DOUT);
    // self_out = input @ Wio^T + bio  -> output[:, 0:256]
    tc_gemm_kernel<1, 8, false><<<N_NODES / 128, 128, SMEM1>>>(input, Wior, bio, obp, DCAT);

    // keys|values = neighbor_inputs @ [Wk;Wv]^T + [bk;bv]   (the heavy GEMM)
    tc_gemm_kernel<2, 8, false><<<NROWS / 128, 128, SMEM2>>>(nbr, Wkvp, bkvp, KVp, DCAT);

    // attention: energies -> mask -> softmax -> context
    attn_kernel<<<N_NODES, 256>>>(Qp, KVp, rsp, ctxp);

    // neigh_out = context @ Wno^T + bno -> output[:, 256:512]
    tc_gemm_kernel<1, 8, false><<<N_NODES / 128, 128, SMEM1>>>(ctxp, Wnor, bno, obp + 256, DCAT);

    // gate = relu(output @ Wg^T + bg)
    tc_gemm_kernel<2, 16, true><<<N_NODES / 128, 128, SMEM2>>>(obp, Wgr, bg, gatep, DCAT);

    // BatchNorm statistics (deterministic two-phase) + final elementwise
    bn_partial_kernel<<<128, 256>>>(obp, psump, psqp);
    bn_final_kernel<<<2, 256>>>(psump, psqp, meanp, rstdp);
    final_kernel<<<(N_NODES * DCAT / 4) / 256, 256>>>(obp, gatep, meanp, rstdp, gamma, beta, out);
}

// round 14
// speedup vs baseline: 4.7465x; 1.4590x over previous
#include <cuda_runtime.h>
#include <cstdint>

// Problem constants
#define N_NODES 16384
#define KNBR    32
#define DIN     256
#define DOUT    256
#define DCAT    512
#define NROWS   (N_NODES * KNBR)   // 524288

// ---------------------------------------------------------------------------
// Arch gating: tcgen05 exists only under arch-SPECIFIC (sm_103a) compilation.
// The plain compute_103 PTX pass compiles slow-but-correct fallback bodies.
// ---------------------------------------------------------------------------
#if defined(__CUDA_ARCH__) && \
    (defined(__CUDA_ARCH_FEAT_SM103_ALL) || defined(__CUDA_ARCH_FEAT_SM100_ALL) || \
     (defined(__CUDA_ARCH_SPECIFIC__) && (__CUDA_ARCH_SPECIFIC__ >= 1000)))
#define HAS_TC 1
#else
#define HAS_TC 0
#endif

// ---------------------------------------------------------------------------
// Scratch (static device globals — no runtime allocation)
// ---------------------------------------------------------------------------
__device__ float g_Q[N_NODES * DOUT];
__device__ float g_ctx[N_NODES * DOUT];
__device__ float g_ob[N_NODES * DCAT];
__device__ float g_Wkv[DCAT * DIN];        // packed + tf32-rounded [Wk;Wv]
__device__ float g_Wq_r[DOUT * DIN];
__device__ float g_Wio_r[DOUT * DIN];
__device__ float g_Wno_r[DOUT * DOUT];
__device__ float g_Wg_r[DCAT * DCAT];
__device__ float g_psum[256 * DCAT];
__device__ float g_psq[256 * DCAT];
__device__ float g_mean[DCAT];
__device__ float g_rstd[DCAT];

// ---------------------------------------------------------------------------
// PTX helpers (arch-neutral)
// ---------------------------------------------------------------------------
__device__ __forceinline__ uint32_t smem_u32(const void* p) {
    uint32_t a;
    asm("{ .reg .u64 t; cvta.to.shared.u64 t, %1; cvt.u32.u64 %0, t; }" : "=r"(a) : "l"(p));
    return a;
}
__device__ __forceinline__ uint32_t rna_tf32(float f) {
    uint32_t r;
    asm("cvt.rna.tf32.f32 %0, %1;" : "=r"(r) : "f"(f));
    return r;
}
__device__ __forceinline__ uint32_t sw128(uint32_t off) { return off ^ ((off >> 3) & 0x70); }

#if HAS_TC
// ---------------------------------------------------------------------------
// tcgen05 / async helpers (compiled only for sm_10xa)
// ---------------------------------------------------------------------------
__device__ __forceinline__ uint32_t elect_one() {
    uint32_t p;
    asm volatile("{ .reg .pred P; elect.sync _|P, 0xFFFFFFFF; selp.b32 %0, 1, 0, P; }" : "=r"(p));
    return p;
}

#define TCGEN05_ALLOC(a, n) \
    asm volatile("tcgen05.alloc.cta_group::1.sync.aligned.shared::cta.b32 [%0], %1;" \
                 :: "r"(a), "r"(n) : "memory")
#define TCGEN05_DEALLOC(t, n) \
    asm volatile("tcgen05.dealloc.cta_group::1.sync.aligned.b32 %0, %1;" :: "r"(t), "r"(n))
#define TCGEN05_RELINQ() \
    asm volatile("tcgen05.relinquish_alloc_permit.cta_group::1.sync.aligned;")
#define TCGEN05_COMMIT(m) \
    asm volatile("tcgen05.commit.cta_group::1.mbarrier::arrive::one.shared::cluster.b64 [%0];" \
                 :: "r"(m) : "memory")
#define TCGEN05_FENCE_AFTER()  asm volatile("tcgen05.fence::after_thread_sync;" ::: "memory")
#define TCGEN05_FENCE_BEFORE() asm volatile("tcgen05.fence::before_thread_sync;" ::: "memory")
#define TCGEN05_WAIT_LD()      asm volatile("tcgen05.wait::ld.sync.aligned;" ::: "memory")
#define MBARRIER_INIT(m, c) \
    asm volatile("mbarrier.init.shared.b64 [%0], %1;" :: "r"(m), "r"(c) : "memory")
#define CP_ASYNC16(dst, src) \
    asm volatile("cp.async.cg.shared.global [%0], [%1], 16;" :: "r"(dst), "l"(src) : "memory")
#define CP_ASYNC_COMMIT() asm volatile("cp.async.commit_group;" ::: "memory")
#define CP_ASYNC_WAIT0()  asm volatile("cp.async.wait_group 0;" ::: "memory")

#define MBARRIER_WAIT_PARITY(mbar_smem_addr, phase_parity) do { \
    uint32_t _mbar = (uint32_t)(mbar_smem_addr); \
    uint32_t _parity = (uint32_t)(phase_parity); \
    uint32_t _done; \
    asm volatile( \
        "{\n\t" \
        ".reg .pred p;\n\t" \
        "mbarrier.try_wait.parity.acquire.cta.shared::cta.b64 p, [%1], %2;\n\t" \
        "selp.b32 %0, 1, 0, p;\n\t" \
        "}" \
        : "=r"(_done) : "r"(_mbar), "r"(_parity) : "memory"); \
    if (!_done) { \
        asm volatile( \
            "{\n\t" \
            ".reg .pred P1;\n\t" \
            "WAIT_LOOP_%=:\n\t" \
            "mbarrier.try_wait.parity.acquire.cta.shared::cta.b64 P1, [%0], %1, 0x989680;\n\t" \
            "@P1 bra.uni WAIT_DONE_%=;\n\t" \
            "bra.uni WAIT_LOOP_%=;\n\t" \
            "WAIT_DONE_%=:\n\t" \
            "}" \
            :: "r"(_mbar), "r"(_parity) : "memory"); \
    } \
} while (0)

#define TCGEN05_LD_32X32B_X32(r, tmem_addr) \
    asm volatile( \
        "tcgen05.ld.sync.aligned.32x32b.x32.b32 " \
        "{%0, %1, %2, %3, %4, %5, %6, %7, " \
        " %8, %9, %10, %11, %12, %13, %14, %15, " \
        " %16, %17, %18, %19, %20, %21, %22, %23, " \
        " %24, %25, %26, %27, %28, %29, %30, %31}, [%32];" \
        : "=r"((r)[0]),  "=r"((r)[1]),  "=r"((r)[2]),  "=r"((r)[3]), \
          "=r"((r)[4]),  "=r"((r)[5]),  "=r"((r)[6]),  "=r"((r)[7]), \
          "=r"((r)[8]),  "=r"((r)[9]),  "=r"((r)[10]), "=r"((r)[11]), \
          "=r"((r)[12]), "=r"((r)[13]), "=r"((r)[14]), "=r"((r)[15]), \
          "=r"((r)[16]), "=r"((r)[17]), "=r"((r)[18]), "=r"((r)[19]), \
          "=r"((r)[20]), "=r"((r)[21]), "=r"((r)[22]), "=r"((r)[23]), \
          "=r"((r)[24]), "=r"((r)[25]), "=r"((r)[26]), "=r"((r)[27]), \
          "=r"((r)[28]), "=r"((r)[29]), "=r"((r)[30]), "=r"((r)[31]) \
        : "r"(tmem_addr))

// SW128 K-major SMEM descriptor (LBO=1, SBO=64, version=1, layout=SW128)
__device__ __forceinline__ uint64_t sw128_desc(uint32_t addr) {
    constexpr uint64_t base = (2ull << 61) | (1ull << 46) | (64ull << 32) | (1ull << 16);
    return base | ((uint64_t)(addr >> 4) & 0x3FFFull);
}

// tcgen05 tf32 SS MMA: D[M=128, N=256] += A(smem desc) * B(smem desc)^T
__device__ __forceinline__ void mma_tf32_ss(uint32_t d, uint64_t ad, uint64_t bd,
                                            uint32_t idesc, uint32_t acc) {
    asm volatile(
        "{\n\t"
        ".reg .pred p;\n\t"
        "setp.ne.u32 p, %4, 0;\n\t"
        "tcgen05.mma.cta_group::1.kind::tf32 [%0], %1, %2, %3, p;\n\t"
        "}"
        :: "r"(d), "l"(ad), "l"(bd), "r"(idesc), "r"(acc) : "memory");
}

// idesc: dtype F32 (1<<4), atype TF32 (2<<7), btype TF32 (2<<10), N/8<<17, M/16<<24
static constexpr uint32_t IDESC_TF32_128x256 =
    (1u << 4) | (2u << 7) | (2u << 10) | (32u << 17) | (8u << 24);

// Shared mainloop: stage chunks of A (tf32-rounded) and W (pre-rounded), issue
// tcgen05 MMAs accumulating D[128, NT*256] in TMEM. If RS, accumulate per-row
// sums of the staged A into *rs (threads 0..127, thread t = row t).
template <int NT, int NC, bool RS>
__device__ __forceinline__ void tc_mainloop(const float* __restrict__ A,
                                            const float* __restrict__ W,
                                            uint32_t sb, uint32_t tb, size_t bm,
                                            int& ph0, int& ph1, float* rs)
{
    constexpr int NTOT  = NT * 256;
    constexpr int K     = NC * 32;
    constexpr int STAGE = (128 + NTOT) * 128;
    const int tid = threadIdx.x;
    const int wid = tid >> 5;

    const uint32_t aBase0 = sb + 1024;
    const uint32_t bBase0 = aBase0 + 128 * 128;

    for (int c = 0; c < NC; c++) {
        const int      buf = c & 1;
        const uint32_t aB  = aBase0 + buf * STAGE;
        const uint32_t bB  = bBase0 + buf * STAGE;

        if (c >= 2) {
            if (buf == 0) { MBARRIER_WAIT_PARITY(sb + 8,  ph0); ph0 ^= 1; }
            else          { MBARRIER_WAIT_PARITY(sb + 16, ph1); ph1 ^= 1; }
        }

        const int k0 = c * 32;

        // B chunk via cp.async (weights already tf32-rounded in gmem)
        for (int idx = tid; idx < NTOT * 8; idx += 256) {
            const int r = idx >> 3, q = idx & 7;
            const float* src = W + (size_t)r * K + k0 + q * 4;
            CP_ASYNC16(bB + sw128((uint32_t)(r * 128 + q * 16)), src);
        }
        CP_ASYNC_COMMIT();

        // A chunk: LDG + rna tf32 round + swizzled STS
        for (int idx = tid; idx < 128 * 8; idx += 256) {
            const int r = idx >> 3, q = idx & 7;
            float4 v = *(const float4*)(A + (bm + r) * (size_t)K + k0 + q * 4);
            uint32_t x = rna_tf32(v.x), y = rna_tf32(v.y), z = rna_tf32(v.z), w = rna_tf32(v.w);
            uint32_t dst = aB + sw128((uint32_t)(r * 128 + q * 16));
            asm volatile("st.shared.v4.b32 [%0], {%1,%2,%3,%4};"
                         :: "r"(dst), "r"(x), "r"(y), "r"(z), "r"(w) : "memory");
        }
        CP_ASYNC_WAIT0();
        TCGEN05_FENCE_BEFORE();
        __syncthreads();

        // Optional: per-row sums of staged (rounded) A — thread t owns row t
        if (RS && tid < 128) {
            float acc = 0.f;
#pragma unroll
            for (int q = 0; q < 8; q++) {
                uint32_t addr = aB + sw128((uint32_t)(tid * 128 + q * 16));
                float x, y, z, w;
                asm volatile("ld.shared.v4.f32 {%0,%1,%2,%3}, [%4];"
                             : "=f"(x), "=f"(y), "=f"(z), "=f"(w) : "r"(addr));
                acc += x + y + z + w;
            }
            *rs += acc;
        }

        if (wid == 0) {
            TCGEN05_FENCE_AFTER();
            if (elect_one()) {
                const uint64_t ad  = sw128_desc(aB);
                const uint64_t bd0 = sw128_desc(bB);
                const uint64_t bd1 = sw128_desc(bB + 256 * 128);
#pragma unroll
                for (int s = 0; s < 4; s++) {
                    const uint32_t acc = (c > 0 || s > 0) ? 1u : 0u;
                    mma_tf32_ss(tb,       ad + 2 * s, bd0 + 2 * s, IDESC_TF32_128x256, acc);
                    if (NT == 2)
                        mma_tf32_ss(tb + 256, ad + 2 * s, bd1 + 2 * s, IDESC_TF32_128x256, acc);
                }
                TCGEN05_COMMIT(sb + 8 + buf * 8);
            }
        }
    }
}
#endif  // HAS_TC

// ---------------------------------------------------------------------------
// Generic GEMM: C[m][n] = A[m][:] . W[n][:] + bias[n]
// EPI 0: bias only.   EPI 2: fused gate*relu(batchnorm) — C = out, A = ob,
//        out[r][c] = relu(D[r][c]+bias[c]) * relu(gamma[c]*(A[r][c]-mean[c])*rstd[c]+beta[c])
// ---------------------------------------------------------------------------
template <int NT, int NC, int EPI>
__global__ void __launch_bounds__(256, 1)
tc_gemm_kernel(const float* __restrict__ A, const float* __restrict__ W,
               const float* __restrict__ bias, float* __restrict__ C, int ldc,
               const float* __restrict__ mean, const float* __restrict__ rstd,
               const float* __restrict__ gamma, const float* __restrict__ beta)
{
    constexpr int NTOT = NT * 256;
    constexpr int K    = NC * 32;

#if HAS_TC
    extern __shared__ __align__(1024) char smem[];
    const uint32_t sb  = smem_u32(smem);
    const int      tid = threadIdx.x;
    const int      wid = tid >> 5, lane = tid & 31;
    const size_t   bm  = (size_t)blockIdx.x * 128;

    if (wid == 0) TCGEN05_ALLOC(sb, 512);
    if (tid == 0) { MBARRIER_INIT(sb + 8, 1); MBARRIER_INIT(sb + 16, 1); }
    __syncthreads();
    uint32_t tb;
    asm volatile("ld.shared.b32 %0, [%1];" : "=r"(tb) : "r"(sb));

    int ph0 = 0, ph1 = 0;
    float rs_dummy = 0.f;
    tc_mainloop<NT, NC, false>(A, W, sb, tb, bm, ph0, ph1, &rs_dummy);

    MBARRIER_WAIT_PARITY(sb + 8,  ph0);
    MBARRIER_WAIT_PARITY(sb + 16, ph1);
    TCGEN05_FENCE_AFTER();

    if (wid < 4) {
        const size_t row  = bm + (size_t)wid * 32 + lane;
        float* const crow = C + row * (size_t)ldc;
#pragma unroll
        for (int g = 0; g < NT * 8; g++) {
            uint32_t r[32];
            TCGEN05_LD_32X32B_X32(r, tb + g * 32);
            TCGEN05_WAIT_LD();
            const int c0 = g * 32;
#pragma unroll
            for (int j = 0; j < 32; j += 4) {
                float4 o;
                o.x = __uint_as_float(r[j + 0]) + bias[c0 + j + 0];
                o.y = __uint_as_float(r[j + 1]) + bias[c0 + j + 1];
                o.z = __uint_as_float(r[j + 2]) + bias[c0 + j + 2];
                o.w = __uint_as_float(r[j + 3]) + bias[c0 + j + 3];
                if (EPI == 2) {
                    const int c = c0 + j;
                    float4 x = *(const float4*)(A + row * (size_t)K + c);
                    o.x = fmaxf(o.x, 0.f) *
                          fmaxf(gamma[c+0]*(x.x-mean[c+0])*rstd[c+0]+beta[c+0], 0.f);
                    o.y = fmaxf(o.y, 0.f) *
                          fmaxf(gamma[c+1]*(x.y-mean[c+1])*rstd[c+1]+beta[c+1], 0.f);
                    o.z = fmaxf(o.z, 0.f) *
                          fmaxf(gamma[c+2]*(x.z-mean[c+2])*rstd[c+2]+beta[c+2], 0.f);
                    o.w = fmaxf(o.w, 0.f) *
                          fmaxf(gamma[c+3]*(x.w-mean[c+3])*rstd[c+3]+beta[c+3], 0.f);
                }
                *(float4*)(crow + c0 + j) = o;
            }
        }
        TCGEN05_FENCE_BEFORE();
    }
    __syncthreads();
    if (wid == 0) { TCGEN05_RELINQ(); TCGEN05_DEALLOC(tb, 512); }

#else  // ----- generic fallback (correctness-only; never runs on sm_103a) ----
    extern __shared__ __align__(1024) char smem[];
    float (*As)[128] = (float (*)[128])smem;
    float (*Bs)[32]  = (float (*)[32])(smem + 16 * 128 * 4);
    const int    tid = threadIdx.x;
    const size_t bm  = (size_t)blockIdx.x * 128;
    const int    ty  = tid >> 3, tx = tid & 7;   // 32 x 8 grid
    const int    m0  = ty * 4,  n0 = tx * 4;

    for (int nb = 0; nb < NTOT; nb += 32) {
        float acc[4][4];
#pragma unroll
        for (int i = 0; i < 4; i++)
#pragma unroll
            for (int j = 0; j < 4; j++) acc[i][j] = 0.f;

        for (int k0 = 0; k0 < K; k0 += 16) {
            __syncthreads();
            for (int idx = tid; idx < 16 * 128; idx += 256) {
                const int m = idx & 127, kk = idx >> 7;
                As[kk][m] = A[(bm + m) * (size_t)K + k0 + kk];
            }
            for (int idx = tid; idx < 16 * 32; idx += 256) {
                const int n = idx & 31, kk = idx >> 5;
                Bs[kk][n] = W[(size_t)(nb + n) * K + k0 + kk];
            }
            __syncthreads();
#pragma unroll
            for (int kk = 0; kk < 16; kk++)
#pragma unroll
                for (int i = 0; i < 4; i++) {
                    const float a = As[kk][m0 + i];
#pragma unroll
                    for (int j = 0; j < 4; j++) acc[i][j] = fmaf(a, Bs[kk][n0 + j], acc[i][j]);
                }
        }
#pragma unroll
        for (int i = 0; i < 4; i++)
#pragma unroll
            for (int j = 0; j < 4; j++) {
                const size_t row = bm + m0 + i;
                const int    c   = nb + n0 + j;
                float o = acc[i][j] + bias[c];
                if (EPI == 2) {
                    float x = A[row * (size_t)K + c];
                    o = fmaxf(o, 0.f) * fmaxf(gamma[c]*(x-mean[c])*rstd[c]+beta[c], 0.f);
                }
                C[row * (size_t)ldc + c] = o;
            }
    }
#endif
}

// ---------------------------------------------------------------------------
// Fused KV-projection + attention kernel.
// Per CTA: 128 rows = 4 nodes x 32 neighbors. Mainloop computes D = nbr_tile @
// [Wk;Wv]^T in TMEM (keys cols 0-255, values cols 256-511) while accumulating
// per-row input sums (padding mask). Epilogue (warps 0-3, warp = node,
// lane = neighbor): energies = LDTM(keys).q + bk.q -> mask -> warp softmax ->
// context via smem transpose of att*LDTM(values), + bv. Writes ctx only.
// ---------------------------------------------------------------------------
__global__ void __launch_bounds__(256, 1)
kv_attn_kernel(const float* __restrict__ nbr, const float* __restrict__ Wkv,
               const float* __restrict__ Q, const float* __restrict__ bk,
               const float* __restrict__ bv, float* __restrict__ ctx)
{
#if HAS_TC
    extern __shared__ __align__(1024) char smem[];
    const uint32_t sb  = smem_u32(smem);
    const int      tid = threadIdx.x;
    const int      wid = tid >> 5, lane = tid & 31;
    const size_t   bm  = (size_t)blockIdx.x * 128;

    if (wid == 0) TCGEN05_ALLOC(sb, 512);
    if (tid == 0) { MBARRIER_INIT(sb + 8, 1); MBARRIER_INIT(sb + 16, 1); }
    __syncthreads();
    uint32_t tb;
    asm volatile("ld.shared.b32 %0, [%1];" : "=r"(tb) : "r"(sb));

    int ph0 = 0, ph1 = 0;
    float rs = 0.f;   // row-sum of this thread's A row (tid < 128: row bm+tid)
    tc_mainloop<2, 8, true>(nbr, Wkv, sb, tb, bm, ph0, ph1, &rs);

    MBARRIER_WAIT_PARITY(sb + 8,  ph0);
    MBARRIER_WAIT_PARITY(sb + 16, ph1);
    TCGEN05_FENCE_AFTER();

    if (wid < 4) {
        const size_t node = (size_t)blockIdx.x * 4 + wid;

        // stage q for this node + fold bk.q
        float* qs = (float*)(smem + 1024) + wid * 256;
        float4 q0 = *(const float4*)(Q + node * 256 + lane * 8);
        float4 q1 = *(const float4*)(Q + node * 256 + lane * 8 + 4);
        *(float4*)(qs + lane * 8)     = q0;
        *(float4*)(qs + lane * 8 + 4) = q1;
        float4 b0 = *(const float4*)(bk + lane * 8);
        float4 b1 = *(const float4*)(bk + lane * 8 + 4);
        float bkq = q0.x*b0.x + q0.y*b0.y + q0.z*b0.z + q0.w*b0.w
                  + q1.x*b1.x + q1.y*b1.y + q1.z*b1.z + q1.w*b1.w;
#pragma unroll
        for (int o = 16; o; o >>= 1) bkq += __shfl_xor_sync(0xffffffffu, bkq, o);
        __syncwarp();

        // energies: e[lane] = keys[lane][:] . q + bk.q
        float e = bkq;
#pragma unroll
        for (int g = 0; g < 8; g++) {
            uint32_t r[32];
            TCGEN05_LD_32X32B_X32(r, tb + g * 32);
            TCGEN05_WAIT_LD();
            const float* qp = qs + g * 32;
#pragma unroll
            for (int j = 0; j < 32; j++) e = fmaf(__uint_as_float(r[j]), qp[j], e);
        }

        // padding mask (row sum == 0) then warp softmax over K=32
        if (rs == 0.0f) e = 1e-12f;
        float m = e;
#pragma unroll
        for (int o = 16; o; o >>= 1) m = fmaxf(m, __shfl_xor_sync(0xffffffffu, m, o));
        float ex = expf(e - m);
        float s = ex;
#pragma unroll
        for (int o = 16; o; o >>= 1) s += __shfl_xor_sync(0xffffffffu, s, o);
        const float a = ex / s;

        // context: ctx[d] = sum_lane a[lane]*v[lane][d] + bv[d]  (smem transpose)
        float* tr = (float*)(smem + 1024) + 1024 + wid * (32 * 33);
#pragma unroll
        for (int g = 0; g < 8; g++) {
            uint32_t r[32];
            TCGEN05_LD_32X32B_X32(r, tb + 256 + g * 32);
            TCGEN05_WAIT_LD();
#pragma unroll
            for (int j = 0; j < 32; j++) tr[j * 33 + lane] = __uint_as_float(r[j]) * a;
            __syncwarp();
            float c = bv[g * 32 + lane];
            const float* trow = tr + lane * 33;
#pragma unroll
            for (int i = 0; i < 32; i++) c += trow[i];
            ctx[node * 256 + g * 32 + lane] = c;
            __syncwarp();
        }
        TCGEN05_FENCE_BEFORE();
    }
    __syncthreads();
    if (wid == 0) { TCGEN05_RELINQ(); TCGEN05_DEALLOC(tb, 512); }

#else  // ----- generic fallback (correctness-only; never runs on sm_103a) ----
    const int    tid = threadIdx.x;
    const size_t bm  = (size_t)blockIdx.x * 128;
    __shared__ float att_s[128];

    if (tid < 128) {
        const size_t row  = bm + tid;
        const size_t node = row >> 5;
        float rsum = 0.f;
        for (int i = 0; i < DIN; i++) rsum += nbr[row * DIN + i];
        float e = 0.f;
        for (int d = 0; d < DOUT; d++) {
            float kd = bk[d];
            for (int i = 0; i < DIN; i++) kd = fmaf(nbr[row * DIN + i], Wkv[(size_t)d * DIN + i], kd);
            e = fmaf(kd, Q[node * DOUT + d], e);
        }
        if (rsum == 0.f) e = 1e-12f;
        float m = e;
        for (int o = 16; o; o >>= 1) m = fmaxf(m, __shfl_xor_sync(0xffffffffu, m, o));
        float ex = expf(e - m);
        float s = ex;
        for (int o = 16; o; o >>= 1) s += __shfl_xor_sync(0xffffffffu, s, o);
        att_s[tid] = ex / s;
    }
    __syncthreads();

    for (int idx = tid; idx < 4 * DOUT; idx += 256) {
        const int    ln   = idx >> 8;
        const int    d    = idx & 255;
        const size_t node = (size_t)blockIdx.x * 4 + ln;
        float c = bv[d];
        for (int k = 0; k < KNBR; k++) {
            const float* xr = nbr + (node * KNBR + k) * (size_t)DIN;
            float vd = 0.f;
            for (int i = 0; i < DIN; i++) vd = fmaf(xr[i], Wkv[(size_t)(256 + d) * DIN + i], vd);
            c = fmaf(att_s[ln * 32 + k], vd, c);
        }
        ctx[node * DOUT + d] = c;
    }
#endif
}

// ---------------------------------------------------------------------------
// Weight pre-rounding to tf32 (rna)
// ---------------------------------------------------------------------------
__global__ void round_tf32_kernel(const float* __restrict__ src, float* __restrict__ dst, int n)
{
    const int i = blockIdx.x * 256 + threadIdx.x;
    if (i < n) dst[i] = __uint_as_float(rna_tf32(src[i]));
}

// Pack Wkv = [Wk ; Wv] (512 x 256) with tf32 rounding
__global__ void pack_wkv_kernel(const float* __restrict__ Wk, const float* __restrict__ Wv,
                                float* __restrict__ Wkv)
{
    const int nrow = blockIdx.x;
    const int t    = threadIdx.x;
    const float* src = (nrow < DOUT) ? (Wk + (size_t)nrow * DIN)
                                     : (Wv + (size_t)(nrow - DOUT) * DIN);
    Wkv[(size_t)nrow * DIN + t] = __uint_as_float(rna_tf32(src[t]));
}

// ---------------------------------------------------------------------------
// BatchNorm statistics (deterministic two-phase)
// ---------------------------------------------------------------------------
__global__ void __launch_bounds__(256)
bn_partial_kernel(const float* __restrict__ ob, float* __restrict__ psum,
                  float* __restrict__ psq)
{
    const int b = blockIdx.x, t = threadIdx.x;   // 256 blocks x 64 rows
    float s0 = 0, s1 = 0, q0 = 0, q1 = 0;
    for (int r = 0; r < 64; r++) {
        const float* row = ob + ((size_t)b * 64 + r) * DCAT;
        float x0 = row[t], x1 = row[t + 256];
        s0 += x0; q0 += x0 * x0;
        s1 += x1; q1 += x1 * x1;
    }
    psum[b * DCAT + t]       = s0;
    psum[b * DCAT + t + 256] = s1;
    psq[b * DCAT + t]        = q0;
    psq[b * DCAT + t + 256]  = q1;
}

__global__ void bn_final_kernel(const float* __restrict__ psum, const float* __restrict__ psq,
                                float* __restrict__ mean, float* __restrict__ rstd)
{
    const int c = blockIdx.x * 256 + threadIdx.x;
    float s = 0, q = 0;
    for (int b = 0; b < 256; b++) { s += psum[b * DCAT + c]; q += psq[b * DCAT + c]; }
    float m = s / (float)N_NODES;
    float v = q / (float)N_NODES - m * m;
    mean[c] = m;
    rstd[c] = rsqrtf(v + 1e-5f);
}

// ---------------------------------------------------------------------------
// Launch
// ---------------------------------------------------------------------------
extern "C" void kernel_launch(void* const* d_in, const int* in_sizes, int n_in,
                              void* d_out, int out_size)
{
    const float* input = (const float*)d_in[0];
    const float* nbr   = (const float*)d_in[1];
    const float* Wq    = (const float*)d_in[2];
    const float* bq    = (const float*)d_in[3];
    const float* Wk    = (const float*)d_in[4];
    const float* bk    = (const float*)d_in[5];
    const float* Wv    = (const float*)d_in[6];
    const float* bv    = (const float*)d_in[7];
    const float* Wno   = (const float*)d_in[8];
    const float* bno   = (const float*)d_in[9];
    const float* Wio   = (const float*)d_in[10];
    const float* bio   = (const float*)d_in[11];
    const float* Wg    = (const float*)d_in[12];
    const float* bg    = (const float*)d_in[13];
    const float* gamma = (const float*)d_in[14];
    const float* beta  = (const float*)d_in[15];
    float* out = (float*)d_out;

    float *Qp, *ctxp, *obp, *Wkvp, *Wqr, *Wior, *Wnor, *Wgr;
    float *psump, *psqp, *meanp, *rstdp;
    cudaGetSymbolAddress((void**)&Qp,    g_Q);
    cudaGetSymbolAddress((void**)&ctxp,  g_ctx);
    cudaGetSymbolAddress((void**)&obp,   g_ob);
    cudaGetSymbolAddress((void**)&Wkvp,  g_Wkv);
    cudaGetSymbolAddress((void**)&Wqr,   g_Wq_r);
    cudaGetSymbolAddress((void**)&Wior,  g_Wio_r);
    cudaGetSymbolAddress((void**)&Wnor,  g_Wno_r);
    cudaGetSymbolAddress((void**)&Wgr,   g_Wg_r);
    cudaGetSymbolAddress((void**)&psump, g_psum);
    cudaGetSymbolAddress((void**)&psqp,  g_psq);
    cudaGetSymbolAddress((void**)&meanp, g_mean);
    cudaGetSymbolAddress((void**)&rstdp, g_rstd);

    // Dynamic SMEM: 1024 header + 2 buffers of (128+NTOT)*128 bytes
    const int SMEM1 = 1024 + 2 * (128 + 256) * 128;   //  99328
    const int SMEM2 = 1024 + 2 * (128 + 512) * 128;   // 164864
    cudaFuncSetAttribute(tc_gemm_kernel<1, 8,  0>, cudaFuncAttributeMaxDynamicSharedMemorySize, SMEM1);
    cudaFuncSetAttribute(tc_gemm_kernel<2, 16, 2>, cudaFuncAttributeMaxDynamicSharedMemorySize, SMEM2);
    cudaFuncSetAttribute(kv_attn_kernel,           cudaFuncAttributeMaxDynamicSharedMemorySize, SMEM2);

    // Weight prep (tf32 rounding)
    round_tf32_kernel<<<(DOUT * DIN + 255) / 256, 256>>>(Wq,  Wqr,  DOUT * DIN);
    round_tf32_kernel<<<(DOUT * DIN + 255) / 256, 256>>>(Wio, Wior, DOUT * DIN);
    round_tf32_kernel<<<(DOUT * DOUT + 255) / 256, 256>>>(Wno, Wnor, DOUT * DOUT);
    round_tf32_kernel<<<(DCAT * DCAT + 255) / 256, 256>>>(Wg,  Wgr,  DCAT * DCAT);
    pack_wkv_kernel<<<DCAT, 256>>>(Wk, Wv, Wkvp);

    // queries = input @ Wq^T + bq
    tc_gemm_kernel<1, 8, 0><<<N_NODES / 128, 256, SMEM1>>>(
        input, Wqr, bq, Qp, DOUT, nullptr, nullptr, nullptr, nullptr);
    // self_out = input @ Wio^T + bio -> output[:, 0:256]
    tc_gemm_kernel<1, 8, 0><<<N_NODES / 128, 256, SMEM1>>>(
        input, Wior, bio, obp, DCAT, nullptr, nullptr, nullptr, nullptr);

    // fused: keys|values projection + masked softmax attention -> context
    kv_attn_kernel<<<NROWS / 128, 256, SMEM2>>>(nbr, Wkvp, Qp, bk, bv, ctxp);

    // neigh_out = context @ Wno^T + bno -> output[:, 256:512]
    tc_gemm_kernel<1, 8, 0><<<N_NODES / 128, 256, SMEM1>>>(
        ctxp, Wnor, bno, obp + 256, DCAT, nullptr, nullptr, nullptr, nullptr);

    // BatchNorm statistics (needed before fused gate epilogue)
    bn_partial_kernel<<<256, 256>>>(obp, psump, psqp);
    bn_final_kernel<<<2, 256>>>(psump, psqp, meanp, rstdp);

    // gate GEMM with fused epilogue: out = relu(ob@Wg^T+bg) * relu(BN(ob))
    tc_gemm_kernel<2, 16, 2><<<N_NODES / 128, 256, SMEM2>>>(
        obp, Wgr, bg, out, DCAT, meanp, rstdp, gamma, beta);
}

// round 15
// speedup vs baseline: 4.9959x; 1.0525x over previous
#include <cuda_runtime.h>
#include <cstdint>

// Problem constants
#define N_NODES 16384
#define KNBR    32
#define DIN     256
#define DOUT    256
#define DCAT    512
#define NROWS   (N_NODES * KNBR)   // 524288

// ---------------------------------------------------------------------------
// Arch gating: tcgen05 exists only under arch-SPECIFIC (sm_103a) compilation.
// The plain compute_103 PTX pass compiles slow-but-correct fallback bodies.
// ---------------------------------------------------------------------------
#if defined(__CUDA_ARCH__) && \
    (defined(__CUDA_ARCH_FEAT_SM103_ALL) || defined(__CUDA_ARCH_FEAT_SM100_ALL) || \
     (defined(__CUDA_ARCH_SPECIFIC__) && (__CUDA_ARCH_SPECIFIC__ >= 1000)))
#define HAS_TC 1
#else
#define HAS_TC 0
#endif

// ---------------------------------------------------------------------------
// Scratch (static device globals — no runtime allocation).
// Packed weights are stored as chunk-major swizzled SMEM images:
//   chunk c (32 K-cols) occupies ntot*128 bytes; within it, the 16-byte group
//   for (row r, quad q) lives at sw128(r*128 + q*16).
// ---------------------------------------------------------------------------
__device__ float g_Q[N_NODES * DOUT];
__device__ float g_ctx[N_NODES * DOUT];
__device__ float g_ob[N_NODES * DCAT];
__device__ __align__(128) float g_Wqio_pk[DCAT * DIN];   // [Wq;Wio] packed
__device__ __align__(128) float g_Wkv_pk[DCAT * DIN];    // [Wk;Wv] packed
__device__ __align__(128) float g_Wno_pk[DOUT * DOUT];
__device__ __align__(128) float g_Wg_pk[DCAT * DCAT];
__device__ float g_psum[256 * DCAT];
__device__ float g_psq[256 * DCAT];
__device__ float g_mean[DCAT];
__device__ float g_rstd[DCAT];

// ---------------------------------------------------------------------------
// Helpers (arch-neutral)
// ---------------------------------------------------------------------------
__device__ __forceinline__ uint32_t smem_u32(const void* p) {
    uint32_t a;
    asm("{ .reg .u64 t; cvta.to.shared.u64 t, %1; cvt.u32.u64 %0, t; }" : "=r"(a) : "l"(p));
    return a;
}
__device__ __forceinline__ uint32_t rna_tf32(float f) {
    uint32_t r;
    asm("cvt.rna.tf32.f32 %0, %1;" : "=r"(r) : "f"(f));
    return r;
}
__device__ __forceinline__ uint32_t sw128(uint32_t off) { return off ^ ((off >> 3) & 0x70); }

// Read element (r, k) of a packed weight image with ntot rows
__device__ __forceinline__ float w_packed(const float* Wp, int ntot, int r, int k) {
    return Wp[(size_t)(k >> 5) * ((size_t)ntot * 32) +
              (sw128((uint32_t)((r << 7) + ((k & 31) << 2))) >> 2)];
}

#if HAS_TC
// ---------------------------------------------------------------------------
// tcgen05 / async helpers (compiled only for sm_10xa)
// ---------------------------------------------------------------------------
__device__ __forceinline__ uint32_t elect_one() {
    uint32_t p;
    asm volatile("{ .reg .pred P; elect.sync _|P, 0xFFFFFFFF; selp.b32 %0, 1, 0, P; }" : "=r"(p));
    return p;
}

#define TCGEN05_ALLOC(a, n) \
    asm volatile("tcgen05.alloc.cta_group::1.sync.aligned.shared::cta.b32 [%0], %1;" \
                 :: "r"(a), "r"(n) : "memory")
#define TCGEN05_DEALLOC(t, n) \
    asm volatile("tcgen05.dealloc.cta_group::1.sync.aligned.b32 %0, %1;" :: "r"(t), "r"(n))
#define TCGEN05_RELINQ() \
    asm volatile("tcgen05.relinquish_alloc_permit.cta_group::1.sync.aligned;")
#define TCGEN05_COMMIT(m) \
    asm volatile("tcgen05.commit.cta_group::1.mbarrier::arrive::one.shared::cluster.b64 [%0];" \
                 :: "r"(m) : "memory")
#define TCGEN05_FENCE_AFTER()  asm volatile("tcgen05.fence::after_thread_sync;" ::: "memory")
#define TCGEN05_FENCE_BEFORE() asm volatile("tcgen05.fence::before_thread_sync;" ::: "memory")
#define TCGEN05_WAIT_LD()      asm volatile("tcgen05.wait::ld.sync.aligned;" ::: "memory")
#define MBARRIER_INIT(m, c) \
    asm volatile("mbarrier.init.shared.b64 [%0], %1;" :: "r"(m), "r"(c) : "memory")
#define MBARRIER_EXPECT_TX(m, b) \
    asm volatile("mbarrier.arrive.expect_tx.shared.b64 _, [%0], %1;" :: "r"(m), "r"(b) : "memory")
// 1D bulk async copy gmem -> smem, completion via mbarrier complete_tx
#define CP_ASYNC_BULK_G2S(dst, src, bytes, mbar) \
    asm volatile("cp.async.bulk.shared::cluster.global.mbarrier::complete_tx::bytes " \
                 "[%0], [%1], %2, [%3];" \
                 :: "r"(dst), "l"(src), "r"(bytes), "r"(mbar) : "memory")

#define MBARRIER_WAIT_PARITY(mbar_smem_addr, phase_parity) do { \
    uint32_t _mbar = (uint32_t)(mbar_smem_addr); \
    uint32_t _parity = (uint32_t)(phase_parity); \
    uint32_t _done; \
    asm volatile( \
        "{\n\t" \
        ".reg .pred p;\n\t" \
        "mbarrier.try_wait.parity.acquire.cta.shared::cta.b64 p, [%1], %2;\n\t" \
        "selp.b32 %0, 1, 0, p;\n\t" \
        "}" \
        : "=r"(_done) : "r"(_mbar), "r"(_parity) : "memory"); \
    if (!_done) { \
        asm volatile( \
            "{\n\t" \
            ".reg .pred P1;\n\t" \
            "WAIT_LOOP_%=:\n\t" \
            "mbarrier.try_wait.parity.acquire.cta.shared::cta.b64 P1, [%0], %1, 0x989680;\n\t" \
            "@P1 bra.uni WAIT_DONE_%=;\n\t" \
            "bra.uni WAIT_LOOP_%=;\n\t" \
            "WAIT_DONE_%=:\n\t" \
            "}" \
            :: "r"(_mbar), "r"(_parity) : "memory"); \
    } \
} while (0)

#define TCGEN05_LD_32X32B_X32(r, tmem_addr) \
    asm volatile( \
        "tcgen05.ld.sync.aligned.32x32b.x32.b32 " \
        "{%0, %1, %2, %3, %4, %5, %6, %7, " \
        " %8, %9, %10, %11, %12, %13, %14, %15, " \
        " %16, %17, %18, %19, %20, %21, %22, %23, " \
        " %24, %25, %26, %27, %28, %29, %30, %31}, [%32];" \
        : "=r"((r)[0]),  "=r"((r)[1]),  "=r"((r)[2]),  "=r"((r)[3]), \
          "=r"((r)[4]),  "=r"((r)[5]),  "=r"((r)[6]),  "=r"((r)[7]), \
          "=r"((r)[8]),  "=r"((r)[9]),  "=r"((r)[10]), "=r"((r)[11]), \
          "=r"((r)[12]), "=r"((r)[13]), "=r"((r)[14]), "=r"((r)[15]), \
          "=r"((r)[16]), "=r"((r)[17]), "=r"((r)[18]), "=r"((r)[19]), \
          "=r"((r)[20]), "=r"((r)[21]), "=r"((r)[22]), "=r"((r)[23]), \
          "=r"((r)[24]), "=r"((r)[25]), "=r"((r)[26]), "=r"((r)[27]), \
          "=r"((r)[28]), "=r"((r)[29]), "=r"((r)[30]), "=r"((r)[31]) \
        : "r"(tmem_addr))

// SW128 K-major SMEM descriptor (LBO=1, SBO=64, version=1, layout=SW128)
__device__ __forceinline__ uint64_t sw128_desc(uint32_t addr) {
    constexpr uint64_t base = (2ull << 61) | (1ull << 46) | (64ull << 32) | (1ull << 16);
    return base | ((uint64_t)(addr >> 4) & 0x3FFFull);
}

// tcgen05 tf32 SS MMA: D[M=128, N=256] += A(smem desc) * B(smem desc)^T
__device__ __forceinline__ void mma_tf32_ss(uint32_t d, uint64_t ad, uint64_t bd,
                                            uint32_t idesc, uint32_t acc) {
    asm volatile(
        "{\n\t"
        ".reg .pred p;\n\t"
        "setp.ne.u32 p, %4, 0;\n\t"
        "tcgen05.mma.cta_group::1.kind::tf32 [%0], %1, %2, %3, p;\n\t"
        "}"
        :: "r"(d), "l"(ad), "l"(bd), "r"(idesc), "r"(acc) : "memory");
}

// idesc: dtype F32 (1<<4), atype TF32 (2<<7), btype TF32 (2<<10), N/8<<17, M/16<<24
static constexpr uint32_t IDESC_TF32_128x256 =
    (1u << 4) | (2u << 7) | (2u << 10) | (32u << 17) | (8u << 24);

// ---------------------------------------------------------------------------
// Shared mainloop: B chunks arrive via ONE cp.async.bulk from the prepacked
// swizzled image; A chunks staged by all threads (LDG + tf32 rna + STS).
// D[128, NT*256] accumulates in TMEM across all K. If RS, accumulate per-row
// sums of staged A into *rs (threads 0..127, thread t = row bm+t).
// SMEM header: [0] tmem ptr, [8],[16] MMA-done mbars, [24],[32] B-load mbars.
// ---------------------------------------------------------------------------
template <int NT, int NC, bool RS>
__device__ __forceinline__ void tc_mainloop(const float* __restrict__ A,
                                            const float* __restrict__ Wp,
                                            uint32_t sb, uint32_t tb, size_t bm,
                                            int& ph0, int& ph1, float* rs)
{
    constexpr int      NTOT   = NT * 256;
    constexpr int      K      = NC * 32;
    constexpr int      STAGE  = (128 + NTOT) * 128;
    constexpr uint32_t BBYTES = NTOT * 128;
    const int tid = threadIdx.x;
    const int wid = tid >> 5;

    const uint32_t aBase0 = sb + 1024;
    const uint32_t bBase0 = aBase0 + 128 * 128;

    int phl0 = 0, phl1 = 0;

    for (int c = 0; c < NC; c++) {
        const int      buf = c & 1;
        const uint32_t aB  = aBase0 + buf * STAGE;
        const uint32_t bB  = bBase0 + buf * STAGE;

        // Buffer reuse guard: MMAs of chunk c-2 on this buffer must be done
        if (c >= 2) {
            if (buf == 0) { MBARRIER_WAIT_PARITY(sb + 8,  ph0); ph0 ^= 1; }
            else          { MBARRIER_WAIT_PARITY(sb + 16, ph1); ph1 ^= 1; }
        }

        // B chunk: single bulk DMA of the prepacked swizzled tile
        if (tid == 0) {
            MBARRIER_EXPECT_TX(sb + 24 + buf * 8, BBYTES);
            CP_ASYNC_BULK_G2S(bB, (const char*)Wp + (size_t)c * BBYTES, BBYTES,
                              sb + 24 + buf * 8);
        }

        // A chunk: LDG + rna tf32 round + swizzled STS
        const int k0 = c * 32;
        for (int idx = tid; idx < 128 * 8; idx += 256) {
            const int r = idx >> 3, q = idx & 7;
            float4 v = *(const float4*)(A + (bm + r) * (size_t)K + k0 + q * 4);
            uint32_t x = rna_tf32(v.x), y = rna_tf32(v.y), z = rna_tf32(v.z), w = rna_tf32(v.w);
            uint32_t dst = aB + sw128((uint32_t)(r * 128 + q * 16));
            asm volatile("st.shared.v4.b32 [%0], {%1,%2,%3,%4};"
                         :: "r"(dst), "r"(x), "r"(y), "r"(z), "r"(w) : "memory");
        }
        TCGEN05_FENCE_BEFORE();
        __syncthreads();

        // Optional per-row sums of staged (rounded) A — thread t owns row t
        if (RS && tid < 128) {
            float acc = 0.f;
#pragma unroll
            for (int q = 0; q < 8; q++) {
                uint32_t addr = aB + sw128((uint32_t)(tid * 128 + q * 16));
                float x, y, z, w;
                asm volatile("ld.shared.v4.f32 {%0,%1,%2,%3}, [%4];"
                             : "=f"(x), "=f"(y), "=f"(z), "=f"(w) : "r"(addr));
                acc += x + y + z + w;
            }
            *rs += acc;
        }

        if (wid == 0) {
            TCGEN05_FENCE_AFTER();
            const int phl = (buf == 0) ? phl0 : phl1;
            if (elect_one()) {
                // B tile must have landed
                MBARRIER_WAIT_PARITY(sb + 24 + buf * 8, phl);
                const uint64_t ad  = sw128_desc(aB);
                const uint64_t bd0 = sw128_desc(bB);
                const uint64_t bd1 = sw128_desc(bB + 256 * 128);
#pragma unroll
                for (int s = 0; s < 4; s++) {
                    const uint32_t acc = (c > 0 || s > 0) ? 1u : 0u;
                    mma_tf32_ss(tb,       ad + 2 * s, bd0 + 2 * s, IDESC_TF32_128x256, acc);
                    if (NT == 2)
                        mma_tf32_ss(tb + 256, ad + 2 * s, bd1 + 2 * s, IDESC_TF32_128x256, acc);
                }
                TCGEN05_COMMIT(sb + 8 + buf * 8);
            }
            if (buf == 0) phl0 ^= 1; else phl1 ^= 1;
        }
    }
}
#endif  // HAS_TC

// ---------------------------------------------------------------------------
// Generic GEMM with split-destination epilogue:
//   D[r][c] = A[r][:] . W[c][:]    (W from packed image)
//   cols 0..255   -> C0[r*ldc0 + c]       + bias0[c]
//   cols 256..511 -> C1[r*ldc1 + (c-256)] + bias1[c-256]   (NT==2 only)
// EPI 0: bias only.
// EPI 2: fused gate epilogue — writes relu(D+bias) * relu(BN(A[r][c])).
// ---------------------------------------------------------------------------
template <int NT, int NC, int EPI>
__global__ void __launch_bounds__(256, 1)
tc_gemm_kernel(const float* __restrict__ A, const float* __restrict__ Wp,
               const float* __restrict__ bias0, const float* __restrict__ bias1,
               float* __restrict__ C0, int ldc0, float* __restrict__ C1, int ldc1,
               const float* __restrict__ mean, const float* __restrict__ rstd,
               const float* __restrict__ gamma, const float* __restrict__ beta)
{
    constexpr int NTOT = NT * 256;
    constexpr int K    = NC * 32;

#if HAS_TC
    extern __shared__ __align__(1024) char smem[];
    const uint32_t sb  = smem_u32(smem);
    const int      tid = threadIdx.x;
    const int      wid = tid >> 5, lane = tid & 31;
    const size_t   bm  = (size_t)blockIdx.x * 128;

    if (wid == 0) TCGEN05_ALLOC(sb, 512);
    if (tid == 0) {
        MBARRIER_INIT(sb + 8, 1);  MBARRIER_INIT(sb + 16, 1);
        MBARRIER_INIT(sb + 24, 1); MBARRIER_INIT(sb + 32, 1);
    }
    __syncthreads();
    uint32_t tb;
    asm volatile("ld.shared.b32 %0, [%1];" : "=r"(tb) : "r"(sb));

    int ph0 = 0, ph1 = 0;
    float rs_dummy = 0.f;
    tc_mainloop<NT, NC, false>(A, Wp, sb, tb, bm, ph0, ph1, &rs_dummy);

    MBARRIER_WAIT_PARITY(sb + 8,  ph0);
    MBARRIER_WAIT_PARITY(sb + 16, ph1);
    TCGEN05_FENCE_AFTER();

    if (wid < 4) {
        const size_t row = bm + (size_t)wid * 32 + lane;
#pragma unroll
        for (int g = 0; g < NT * 8; g++) {
            uint32_t r[32];
            TCGEN05_LD_32X32B_X32(r, tb + g * 32);
            TCGEN05_WAIT_LD();
            const int c0g = g * 32;
            float* const base = (c0g < 256) ? (C0 + row * (size_t)ldc0 + c0g)
                                            : (C1 + row * (size_t)ldc1 + (c0g - 256));
            const float* const bb = (c0g < 256) ? (bias0 + c0g) : (bias1 + (c0g - 256));
#pragma unroll
            for (int j = 0; j < 32; j += 4) {
                float4 o;
                o.x = __uint_as_float(r[j + 0]) + bb[j + 0];
                o.y = __uint_as_float(r[j + 1]) + bb[j + 1];
                o.z = __uint_as_float(r[j + 2]) + bb[j + 2];
                o.w = __uint_as_float(r[j + 3]) + bb[j + 3];
                if (EPI == 2) {
                    const int c = c0g + j;
                    float4 x = *(const float4*)(A + row * (size_t)K + c);
                    o.x = fmaxf(o.x, 0.f) *
                          fmaxf(gamma[c+0]*(x.x-mean[c+0])*rstd[c+0]+beta[c+0], 0.f);
                    o.y = fmaxf(o.y, 0.f) *
                          fmaxf(gamma[c+1]*(x.y-mean[c+1])*rstd[c+1]+beta[c+1], 0.f);
                    o.z = fmaxf(o.z, 0.f) *
                          fmaxf(gamma[c+2]*(x.z-mean[c+2])*rstd[c+2]+beta[c+2], 0.f);
                    o.w = fmaxf(o.w, 0.f) *
                          fmaxf(gamma[c+3]*(x.w-mean[c+3])*rstd[c+3]+beta[c+3], 0.f);
                }
                *(float4*)(base + j) = o;
            }
        }
        TCGEN05_FENCE_BEFORE();
    }
    __syncthreads();
    if (wid == 0) { TCGEN05_RELINQ(); TCGEN05_DEALLOC(tb, 512); }

#else  // ----- generic fallback (correctness-only; never runs on sm_103a) ----
    const int    tid = threadIdx.x;
    const size_t bm  = (size_t)blockIdx.x * 128;
    for (int idx = tid; idx < 128 * NTOT; idx += 256) {
        const size_t row = bm + (idx / NTOT);
        const int    c   = idx % NTOT;
        float acc = (c < 256) ? bias0[c] : bias1[c - 256];
        for (int k = 0; k < K; k++)
            acc = fmaf(A[row * (size_t)K + k], w_packed(Wp, NTOT, c, k), acc);
        if (EPI == 2) {
            float x = A[row * (size_t)K + c];
            acc = fmaxf(acc, 0.f) * fmaxf(gamma[c]*(x-mean[c])*rstd[c]+beta[c], 0.f);
        }
        if (c < 256) C0[row * (size_t)ldc0 + c] = acc;
        else         C1[row * (size_t)ldc1 + (c - 256)] = acc;
    }
#endif
}

// ---------------------------------------------------------------------------
// Fused KV-projection + attention kernel (unchanged math from round 14,
// mainloop now uses bulk-DMA'd prepacked B).
// ---------------------------------------------------------------------------
__global__ void __launch_bounds__(256, 1)
kv_attn_kernel(const float* __restrict__ nbr, const float* __restrict__ Wp,
               const float* __restrict__ Q, const float* __restrict__ bk,
               const float* __restrict__ bv, float* __restrict__ ctx)
{
#if HAS_TC
    extern __shared__ __align__(1024) char smem[];
    const uint32_t sb  = smem_u32(smem);
    const int      tid = threadIdx.x;
    const int      wid = tid >> 5, lane = tid & 31;
    const size_t   bm  = (size_t)blockIdx.x * 128;

    if (wid == 0) TCGEN05_ALLOC(sb, 512);
    if (tid == 0) {
        MBARRIER_INIT(sb + 8, 1);  MBARRIER_INIT(sb + 16, 1);
        MBARRIER_INIT(sb + 24, 1); MBARRIER_INIT(sb + 32, 1);
    }
    __syncthreads();
    uint32_t tb;
    asm volatile("ld.shared.b32 %0, [%1];" : "=r"(tb) : "r"(sb));

    int ph0 = 0, ph1 = 0;
    float rs = 0.f;   // row-sum of this thread's A row (tid < 128: row bm+tid)
    tc_mainloop<2, 8, true>(nbr, Wp, sb, tb, bm, ph0, ph1, &rs);

    MBARRIER_WAIT_PARITY(sb + 8,  ph0);
    MBARRIER_WAIT_PARITY(sb + 16, ph1);
    TCGEN05_FENCE_AFTER();

    if (wid < 4) {
        const size_t node = (size_t)blockIdx.x * 4 + wid;

        // stage q for this node + fold bk.q
        float* qs = (float*)(smem + 1024) + wid * 256;
        float4 q0 = *(const float4*)(Q + node * 256 + lane * 8);
        float4 q1 = *(const float4*)(Q + node * 256 + lane * 8 + 4);
        *(float4*)(qs + lane * 8)     = q0;
        *(float4*)(qs + lane * 8 + 4) = q1;
        float4 b0 = *(const float4*)(bk + lane * 8);
        float4 b1 = *(const float4*)(bk + lane * 8 + 4);
        float bkq = q0.x*b0.x + q0.y*b0.y + q0.z*b0.z + q0.w*b0.w
                  + q1.x*b1.x + q1.y*b1.y + q1.z*b1.z + q1.w*b1.w;
#pragma unroll
        for (int o = 16; o; o >>= 1) bkq += __shfl_xor_sync(0xffffffffu, bkq, o);
        __syncwarp();

        // energies: e[lane] = keys[lane][:] . q + bk.q
        float e = bkq;
#pragma unroll
        for (int g = 0; g < 8; g++) {
            uint32_t r[32];
            TCGEN05_LD_32X32B_X32(r, tb + g * 32);
            TCGEN05_WAIT_LD();
            const float* qp = qs + g * 32;
#pragma unroll
            for (int j = 0; j < 32; j++) e = fmaf(__uint_as_float(r[j]), qp[j], e);
        }

        // padding mask (row sum == 0) then warp softmax over K=32
        if (rs == 0.0f) e = 1e-12f;
        float m = e;
#pragma unroll
        for (int o = 16; o; o >>= 1) m = fmaxf(m, __shfl_xor_sync(0xffffffffu, m, o));
        float ex = expf(e - m);
        float s = ex;
#pragma unroll
        for (int o = 16; o; o >>= 1) s += __shfl_xor_sync(0xffffffffu, s, o);
        const float a = ex / s;

        // context: ctx[d] = sum_lane a[lane]*v[lane][d] + bv[d]  (smem transpose)
        float* tr = (float*)(smem + 1024) + 1024 + wid * (32 * 33);
#pragma unroll
        for (int g = 0; g < 8; g++) {
            uint32_t r[32];
            TCGEN05_LD_32X32B_X32(r, tb + 256 + g * 32);
            TCGEN05_WAIT_LD();
#pragma unroll
            for (int j = 0; j < 32; j++) tr[j * 33 + lane] = __uint_as_float(r[j]) * a;
            __syncwarp();
            float c = bv[g * 32 + lane];
            const float* trow = tr + lane * 33;
#pragma unroll
            for (int i = 0; i < 32; i++) c += trow[i];
            ctx[node * 256 + g * 32 + lane] = c;
            __syncwarp();
        }
        TCGEN05_FENCE_BEFORE();
    }
    __syncthreads();
    if (wid == 0) { TCGEN05_RELINQ(); TCGEN05_DEALLOC(tb, 512); }

#else  // ----- generic fallback (correctness-only; never runs on sm_103a) ----
    const int    tid = threadIdx.x;
    const size_t bm  = (size_t)blockIdx.x * 128;
    __shared__ float att_s[128];

    if (tid < 128) {
        const size_t row  = bm + tid;
        const size_t node = row >> 5;
        float rsum = 0.f;
        for (int i = 0; i < DIN; i++) rsum += nbr[row * DIN + i];
        float e = 0.f;
        for (int d = 0; d < DOUT; d++) {
            float kd = bk[d];
            for (int i = 0; i < DIN; i++)
                kd = fmaf(nbr[row * DIN + i], w_packed(Wp, DCAT, d, i), kd);
            e = fmaf(kd, Q[node * DOUT + d], e);
        }
        if (rsum == 0.f) e = 1e-12f;
        float m = e;
        for (int o = 16; o; o >>= 1) m = fmaxf(m, __shfl_xor_sync(0xffffffffu, m, o));
        float ex = expf(e - m);
        float s = ex;
        for (int o = 16; o; o >>= 1) s += __shfl_xor_sync(0xffffffffu, s, o);
        att_s[tid] = ex / s;
    }
    __syncthreads();

    for (int idx = tid; idx < 4 * DOUT; idx += 256) {
        const int    ln   = idx >> 8;
        const int    d    = idx & 255;
        const size_t node = (size_t)blockIdx.x * 4 + ln;
        float c = bv[d];
        for (int k = 0; k < KNBR; k++) {
            const float* xr = nbr + (node * KNBR + k) * (size_t)DIN;
            float vd = 0.f;
            for (int i = 0; i < DIN; i++)
                vd = fmaf(xr[i], w_packed(Wp, DCAT, 256 + d, i), vd);
            c = fmaf(att_s[ln * 32 + k], vd, c);
        }
        ctx[node * DOUT + d] = c;
    }
#endif
}

// ---------------------------------------------------------------------------
// Weight packing: rows [0,256) from src0, rows [256, ntot) from src1;
// tf32-round and store into the chunk-major swizzled SMEM image.
// grid = (ntot/32, K/32), block = 256.
// ---------------------------------------------------------------------------
__global__ void pack_w_kernel(const float* __restrict__ src0, const float* __restrict__ src1,
                              float* __restrict__ dst, int K, int ntot)
{
    const int c = blockIdx.y;
    const int r = blockIdx.x * 32 + (threadIdx.x >> 3);
    const int q = threadIdx.x & 7;
    const float* src = (r < 256) ? (src0 + (size_t)r * K) : (src1 + (size_t)(r - 256) * K);
    float4 v = *(const float4*)(src + c * 32 + q * 4);
    float4 o;
    o.x = __uint_as_float(rna_tf32(v.x));
    o.y = __uint_as_float(rna_tf32(v.y));
    o.z = __uint_as_float(rna_tf32(v.z));
    o.w = __uint_as_float(rna_tf32(v.w));
    *(float4*)(dst + (size_t)c * ((size_t)ntot * 32) +
               (sw128((uint32_t)(r * 128 + q * 16)) >> 2)) = o;
}

// ---------------------------------------------------------------------------
// BatchNorm statistics (deterministic two-phase)
// ---------------------------------------------------------------------------
__global__ void __launch_bounds__(256)
bn_partial_kernel(const float* __restrict__ ob, float* __restrict__ psum,
                  float* __restrict__ psq)
{
    const int b = blockIdx.x, t = threadIdx.x;   // 256 blocks x 64 rows
    float s0 = 0, s1 = 0, q0 = 0, q1 = 0;
    for (int r = 0; r < 64; r++) {
        const float* row = ob + ((size_t)b * 64 + r) * DCAT;
        float x0 = row[t], x1 = row[t + 256];
        s0 += x0; q0 += x0 * x0;
        s1 += x1; q1 += x1 * x1;
    }
    psum[b * DCAT + t]       = s0;
    psum[b * DCAT + t + 256] = s1;
    psq[b * DCAT + t]        = q0;
    psq[b * DCAT + t + 256]  = q1;
}

__global__ void bn_final_kernel(const float* __restrict__ psum, const float* __restrict__ psq,
                                float* __restrict__ mean, float* __restrict__ rstd)
{
    const int c = blockIdx.x * 256 + threadIdx.x;
    float s = 0, q = 0;
    for (int b = 0; b < 256; b++) { s += psum[b * DCAT + c]; q += psq[b * DCAT + c]; }
    float m = s / (float)N_NODES;
    float v = q / (float)N_NODES - m * m;
    mean[c] = m;
    rstd[c] = rsqrtf(v + 1e-5f);
}

// ---------------------------------------------------------------------------
// Launch
// ---------------------------------------------------------------------------
extern "C" void kernel_launch(void* const* d_in, const int* in_sizes, int n_in,
                              void* d_out, int out_size)
{
    const float* input = (const float*)d_in[0];
    const float* nbr   = (const float*)d_in[1];
    const float* Wq    = (const float*)d_in[2];
    const float* bq    = (const float*)d_in[3];
    const float* Wk    = (const float*)d_in[4];
    const float* bk    = (const float*)d_in[5];
    const float* Wv    = (const float*)d_in[6];
    const float* bv    = (const float*)d_in[7];
    const float* Wno   = (const float*)d_in[8];
    const float* bno   = (const float*)d_in[9];
    const float* Wio   = (const float*)d_in[10];
    const float* bio   = (const float*)d_in[11];
    const float* Wg    = (const float*)d_in[12];
    const float* bg    = (const float*)d_in[13];
    const float* gamma = (const float*)d_in[14];
    const float* beta  = (const float*)d_in[15];
    float* out = (float*)d_out;

    float *Qp, *ctxp, *obp, *Wqiop, *Wkvp, *Wnop, *Wgp;
    float *psump, *psqp, *meanp, *rstdp;
    cudaGetSymbolAddress((void**)&Qp,    g_Q);
    cudaGetSymbolAddress((void**)&ctxp,  g_ctx);
    cudaGetSymbolAddress((void**)&obp,   g_ob);
    cudaGetSymbolAddress((void**)&Wqiop, g_Wqio_pk);
    cudaGetSymbolAddress((void**)&Wkvp,  g_Wkv_pk);
    cudaGetSymbolAddress((void**)&Wnop,  g_Wno_pk);
    cudaGetSymbolAddress((void**)&Wgp,   g_Wg_pk);
    cudaGetSymbolAddress((void**)&psump, g_psum);
    cudaGetSymbolAddress((void**)&psqp,  g_psq);
    cudaGetSymbolAddress((void**)&meanp, g_mean);
    cudaGetSymbolAddress((void**)&rstdp, g_rstd);

    // Dynamic SMEM: 1024 header + 2 buffers of (128+NTOT)*128 bytes
    const int SMEM1 = 1024 + 2 * (128 + 256) * 128;   //  99328
    const int SMEM2 = 1024 + 2 * (128 + 512) * 128;   // 164864
    cudaFuncSetAttribute(tc_gemm_kernel<2, 8,  0>, cudaFuncAttributeMaxDynamicSharedMemorySize, SMEM2);
    cudaFuncSetAttribute(tc_gemm_kernel<1, 8,  0>, cudaFuncAttributeMaxDynamicSharedMemorySize, SMEM1);
    cudaFuncSetAttribute(tc_gemm_kernel<2, 16, 2>, cudaFuncAttributeMaxDynamicSharedMemorySize, SMEM2);
    cudaFuncSetAttribute(kv_attn_kernel,           cudaFuncAttributeMaxDynamicSharedMemorySize, SMEM2);

    // Pack weights into swizzled chunk-major images (tf32-rounded)
    pack_w_kernel<<<dim3(16, 8),  256>>>(Wq,  Wio,            Wqiop, DIN,  DCAT);
    pack_w_kernel<<<dim3(16, 8),  256>>>(Wk,  Wv,             Wkvp,  DIN,  DCAT);
    pack_w_kernel<<<dim3(8,  8),  256>>>(Wno, Wno,            Wnop,  DOUT, DOUT);
    pack_w_kernel<<<dim3(16, 16), 256>>>(Wg,  Wg + 256 * DCAT, Wgp,  DCAT, DCAT);

    // fused Q + self projections: [queries | self_out] = input @ [Wq;Wio]^T
    tc_gemm_kernel<2, 8, 0><<<N_NODES / 128, 256, SMEM2>>>(
        input, Wqiop, bq, bio, Qp, DOUT, obp, DCAT,
        nullptr, nullptr, nullptr, nullptr);

    // fused: keys|values projection + masked softmax attention -> context
    kv_attn_kernel<<<NROWS / 128, 256, SMEM2>>>(nbr, Wkvp, Qp, bk, bv, ctxp);

    // neigh_out = context @ Wno^T + bno -> output[:, 256:512]
    tc_gemm_kernel<1, 8, 0><<<N_NODES / 128, 256, SMEM1>>>(
        ctxp, Wnop, bno, bno, obp + 256, DCAT, nullptr, 0,
        nullptr, nullptr, nullptr, nullptr);

    // BatchNorm statistics (needed before fused gate epilogue)
    bn_partial_kernel<<<256, 256>>>(obp, psump, psqp);
    bn_final_kernel<<<2, 256>>>(psump, psqp, meanp, rstdp);

    // gate GEMM with fused epilogue: out = relu(ob@Wg^T+bg) * relu(BN(ob))
    tc_gemm_kernel<2, 16, 2><<<N_NODES / 128, 256, SMEM2>>>(
        obp, Wgp, bg, bg + 256, out, DCAT, out + 256, DCAT,
        meanp, rstdp, gamma, beta);
}

// round 16
// speedup vs baseline: 8.8545x; 1.7724x over previous
#include <cuda_runtime.h>
#include <cstdint>

// Problem constants
#define N_NODES 16384
#define KNBR    32
#define DIN     256
#define DOUT    256
#define DCAT    512
#define NROWS   (N_NODES * KNBR)   // 524288

// ---------------------------------------------------------------------------
// Arch gating: tcgen05 exists only under arch-SPECIFIC (sm_103a) compilation.
// The plain compute_103 PTX pass compiles slow-but-correct fallback bodies.
// ---------------------------------------------------------------------------
#if defined(__CUDA_ARCH__) && \
    (defined(__CUDA_ARCH_FEAT_SM103_ALL) || defined(__CUDA_ARCH_FEAT_SM100_ALL) || \
     (defined(__CUDA_ARCH_SPECIFIC__) && (__CUDA_ARCH_SPECIFIC__ >= 1000)))
#define HAS_TC 1
#else
#define HAS_TC 0
#endif

// ---------------------------------------------------------------------------
// Scratch (static device globals — no runtime allocation).
// Packed weights: chunk-major swizzled SMEM images (chunk = 32 K-cols;
// element (r, q) of a chunk at byte sw128(r*128 + q*16)).
// ---------------------------------------------------------------------------
__device__ float g_Q[N_NODES * DOUT];
__device__ float g_ctx[N_NODES * DOUT];
__device__ float g_ob[N_NODES * DCAT];
__device__ __align__(128) float g_Wqio_pk[DCAT * DIN];   // [Wq;Wio] packed
__device__ __align__(128) float g_Wkv_pk[DCAT * DIN];    // [Wk;Wv] packed
__device__ __align__(128) float g_Wno_pk[DOUT * DOUT];
__device__ __align__(128) float g_Wg_pk[DCAT * DCAT];
__device__ float g_psum[256 * DCAT];
__device__ float g_psq[256 * DCAT];
__device__ float g_mean[DCAT];
__device__ float g_rstd[DCAT];

// ---------------------------------------------------------------------------
// Helpers (arch-neutral)
// ---------------------------------------------------------------------------
__device__ __forceinline__ uint32_t smem_u32(const void* p) {
    uint32_t a;
    asm("{ .reg .u64 t; cvta.to.shared.u64 t, %1; cvt.u32.u64 %0, t; }" : "=r"(a) : "l"(p));
    return a;
}
__device__ __forceinline__ uint32_t rna_tf32(float f) {
    uint32_t r;
    asm("cvt.rna.tf32.f32 %0, %1;" : "=r"(r) : "f"(f));
    return r;
}
__device__ __forceinline__ uint32_t sw128(uint32_t off) { return off ^ ((off >> 3) & 0x70); }

// Read element (r, k) of a packed weight image with ntot rows
__device__ __forceinline__ float w_packed(const float* Wp, int ntot, int r, int k) {
    return Wp[(size_t)(k >> 5) * ((size_t)ntot * 32) +
              (sw128((uint32_t)((r << 7) + ((k & 31) << 2))) >> 2)];
}

#if HAS_TC
// ---------------------------------------------------------------------------
// tcgen05 / async helpers (compiled only for sm_10xa)
// ---------------------------------------------------------------------------
__device__ __forceinline__ uint32_t elect_one() {
    uint32_t p;
    asm volatile("{ .reg .pred P; elect.sync _|P, 0xFFFFFFFF; selp.b32 %0, 1, 0, P; }" : "=r"(p));
    return p;
}

#define TCGEN05_ALLOC(a, n) \
    asm volatile("tcgen05.alloc.cta_group::1.sync.aligned.shared::cta.b32 [%0], %1;" \
                 :: "r"(a), "r"(n) : "memory")
#define TCGEN05_DEALLOC(t, n) \
    asm volatile("tcgen05.dealloc.cta_group::1.sync.aligned.b32 %0, %1;" :: "r"(t), "r"(n))
#define TCGEN05_RELINQ() \
    asm volatile("tcgen05.relinquish_alloc_permit.cta_group::1.sync.aligned;")
#define TCGEN05_COMMIT(m) \
    asm volatile("tcgen05.commit.cta_group::1.mbarrier::arrive::one.shared::cluster.b64 [%0];" \
                 :: "r"(m) : "memory")
#define TCGEN05_FENCE_AFTER()  asm volatile("tcgen05.fence::after_thread_sync;" ::: "memory")
#define TCGEN05_FENCE_BEFORE() asm volatile("tcgen05.fence::before_thread_sync;" ::: "memory")
#define TCGEN05_WAIT_LD()      asm volatile("tcgen05.wait::ld.sync.aligned;" ::: "memory")
#define MBARRIER_INIT(m, c) \
    asm volatile("mbarrier.init.shared.b64 [%0], %1;" :: "r"(m), "r"(c) : "memory")
#define MBARRIER_EXPECT_TX(m, b) \
    asm volatile("mbarrier.arrive.expect_tx.shared.b64 _, [%0], %1;" :: "r"(m), "r"(b) : "memory")
#define CP_ASYNC_BULK_G2S(dst, src, bytes, mbar) \
    asm volatile("cp.async.bulk.shared::cluster.global.mbarrier::complete_tx::bytes " \
                 "[%0], [%1], %2, [%3];" \
                 :: "r"(dst), "l"(src), "r"(bytes), "r"(mbar) : "memory")

#define MBARRIER_WAIT_PARITY(mbar_smem_addr, phase_parity) do { \
    uint32_t _mbar = (uint32_t)(mbar_smem_addr); \
    uint32_t _parity = (uint32_t)(phase_parity); \
    uint32_t _done; \
    asm volatile( \
        "{\n\t" \
        ".reg .pred p;\n\t" \
        "mbarrier.try_wait.parity.acquire.cta.shared::cta.b64 p, [%1], %2;\n\t" \
        "selp.b32 %0, 1, 0, p;\n\t" \
        "}" \
        : "=r"(_done) : "r"(_mbar), "r"(_parity) : "memory"); \
    if (!_done) { \
        asm volatile( \
            "{\n\t" \
            ".reg .pred P1;\n\t" \
            "WAIT_LOOP_%=:\n\t" \
            "mbarrier.try_wait.parity.acquire.cta.shared::cta.b64 P1, [%0], %1, 0x989680;\n\t" \
            "@P1 bra.uni WAIT_DONE_%=;\n\t" \
            "bra.uni WAIT_LOOP_%=;\n\t" \
            "WAIT_DONE_%=:\n\t" \
            "}" \
            :: "r"(_mbar), "r"(_parity) : "memory"); \
    } \
} while (0)

#define TCGEN05_LD_32X32B_X32(r, tmem_addr) \
    asm volatile( \
        "tcgen05.ld.sync.aligned.32x32b.x32.b32 " \
        "{%0, %1, %2, %3, %4, %5, %6, %7, " \
        " %8, %9, %10, %11, %12, %13, %14, %15, " \
        " %16, %17, %18, %19, %20, %21, %22, %23, " \
        " %24, %25, %26, %27, %28, %29, %30, %31}, [%32];" \
        : "=r"((r)[0]),  "=r"((r)[1]),  "=r"((r)[2]),  "=r"((r)[3]), \
          "=r"((r)[4]),  "=r"((r)[5]),  "=r"((r)[6]),  "=r"((r)[7]), \
          "=r"((r)[8]),  "=r"((r)[9]),  "=r"((r)[10]), "=r"((r)[11]), \
          "=r"((r)[12]), "=r"((r)[13]), "=r"((r)[14]), "=r"((r)[15]), \
          "=r"((r)[16]), "=r"((r)[17]), "=r"((r)[18]), "=r"((r)[19]), \
          "=r"((r)[20]), "=r"((r)[21]), "=r"((r)[22]), "=r"((r)[23]), \
          "=r"((r)[24]), "=r"((r)[25]), "=r"((r)[26]), "=r"((r)[27]), \
          "=r"((r)[28]), "=r"((r)[29]), "=r"((r)[30]), "=r"((r)[31]) \
        : "r"(tmem_addr))

// SW128 K-major SMEM descriptor (LBO=1, SBO=64, version=1, layout=SW128)
__device__ __forceinline__ uint64_t sw128_desc(uint32_t addr) {
    constexpr uint64_t base = (2ull << 61) | (1ull << 46) | (64ull << 32) | (1ull << 16);
    return base | ((uint64_t)(addr >> 4) & 0x3FFFull);
}

// tcgen05 tf32 SS MMA: D[M=128, N=256] += A(smem desc) * B(smem desc)^T
__device__ __forceinline__ void mma_tf32_ss(uint32_t d, uint64_t ad, uint64_t bd,
                                            uint32_t idesc, uint32_t acc) {
    asm volatile(
        "{\n\t"
        ".reg .pred p;\n\t"
        "setp.ne.u32 p, %4, 0;\n\t"
        "tcgen05.mma.cta_group::1.kind::tf32 [%0], %1, %2, %3, p;\n\t"
        "}"
        :: "r"(d), "l"(ad), "l"(bd), "r"(idesc), "r"(acc) : "memory");
}

// idesc: dtype F32 (1<<4), atype TF32 (2<<7), btype TF32 (2<<10), N/8<<17, M/16<<24
static constexpr uint32_t IDESC_TF32_128x256 =
    (1u << 4) | (2u << 7) | (2u << 10) | (32u << 17) | (8u << 24);

// ---------------------------------------------------------------------------
// Shared mainloop (software-pipelined A): registers hold chunk c's A tile at
// loop entry; after STS we immediately prefetch chunk c+1, hiding LDG latency
// behind sync + MMA issue + buffer-reuse wait. B chunks arrive via one
// cp.async.bulk from the prepacked swizzled image.
// D[128, NT*256] accumulates in TMEM across all K. If RS, per-row sums of the
// staged A accumulate into *rs (threads 0..127, thread t = row bm+t).
// SMEM header: [0] tmem ptr, [8],[16] MMA-done mbars, [24],[32] B-load mbars.
// ---------------------------------------------------------------------------
template <int NT, int NC, bool RS>
__device__ __forceinline__ void tc_mainloop(const float* __restrict__ A,
                                            const float* __restrict__ Wp,
                                            uint32_t sb, uint32_t tb, size_t bm,
                                            int& ph0, int& ph1, float* rs)
{
    constexpr int      NTOT   = NT * 256;
    constexpr int      K      = NC * 32;
    constexpr int      STAGE  = (128 + NTOT) * 128;
    constexpr uint32_t BBYTES = NTOT * 128;
    const int tid = threadIdx.x;
    const int wid = tid >> 5;
    const int r0  = tid >> 3;          // rows r0, r0+32, r0+64, r0+96
    const int q   = tid & 7;

    const uint32_t aBase0 = sb + 1024;
    const uint32_t bBase0 = aBase0 + 128 * 128;

    int phl0 = 0, phl1 = 0;

    // Prefetch chunk 0's A tile
    float4 av[4];
#pragma unroll
    for (int i = 0; i < 4; i++)
        av[i] = *(const float4*)(A + (bm + r0 + 32 * i) * (size_t)K + q * 4);

    for (int c = 0; c < NC; c++) {
        const int      buf = c & 1;
        const uint32_t aB  = aBase0 + buf * STAGE;
        const uint32_t bB  = bBase0 + buf * STAGE;

        // Buffer reuse guard: MMAs of chunk c-2 on this buffer must be done
        if (c >= 2) {
            if (buf == 0) { MBARRIER_WAIT_PARITY(sb + 8,  ph0); ph0 ^= 1; }
            else          { MBARRIER_WAIT_PARITY(sb + 16, ph1); ph1 ^= 1; }
        }

        // B chunk: single bulk DMA of the prepacked swizzled tile
        if (tid == 0) {
            MBARRIER_EXPECT_TX(sb + 24 + buf * 8, BBYTES);
            CP_ASYNC_BULK_G2S(bB, (const char*)Wp + (size_t)c * BBYTES, BBYTES,
                              sb + 24 + buf * 8);
        }

        // Store prefetched A (rna tf32 round) and prefetch chunk c+1
#pragma unroll
        for (int i = 0; i < 4; i++) {
            uint32_t x = rna_tf32(av[i].x), y = rna_tf32(av[i].y),
                     z = rna_tf32(av[i].z), w = rna_tf32(av[i].w);
            uint32_t dst = aB + sw128((uint32_t)((r0 + 32 * i) * 128 + q * 16));
            asm volatile("st.shared.v4.b32 [%0], {%1,%2,%3,%4};"
                         :: "r"(dst), "r"(x), "r"(y), "r"(z), "r"(w) : "memory");
        }
        if (c + 1 < NC) {
#pragma unroll
            for (int i = 0; i < 4; i++)
                av[i] = *(const float4*)(A + (bm + r0 + 32 * i) * (size_t)K +
                                         (c + 1) * 32 + q * 4);
        }
        TCGEN05_FENCE_BEFORE();
        __syncthreads();

        // Optional per-row sums of staged (rounded) A — thread t owns row t
        if (RS && tid < 128) {
            float acc = 0.f;
#pragma unroll
            for (int qq = 0; qq < 8; qq++) {
                uint32_t addr = aB + sw128((uint32_t)(tid * 128 + qq * 16));
                float x, y, z, w;
                asm volatile("ld.shared.v4.f32 {%0,%1,%2,%3}, [%4];"
                             : "=f"(x), "=f"(y), "=f"(z), "=f"(w) : "r"(addr));
                acc += x + y + z + w;
            }
            *rs += acc;
        }

        if (wid == 0) {
            TCGEN05_FENCE_AFTER();
            const int phl = (buf == 0) ? phl0 : phl1;
            if (elect_one()) {
                MBARRIER_WAIT_PARITY(sb + 24 + buf * 8, phl);   // B landed
                const uint64_t ad  = sw128_desc(aB);
                const uint64_t bd0 = sw128_desc(bB);
                const uint64_t bd1 = sw128_desc(bB + 256 * 128);
#pragma unroll
                for (int s = 0; s < 4; s++) {
                    const uint32_t acc = (c > 0 || s > 0) ? 1u : 0u;
                    mma_tf32_ss(tb,       ad + 2 * s, bd0 + 2 * s, IDESC_TF32_128x256, acc);
                    if (NT == 2)
                        mma_tf32_ss(tb + 256, ad + 2 * s, bd1 + 2 * s, IDESC_TF32_128x256, acc);
                }
                TCGEN05_COMMIT(sb + 8 + buf * 8);
            }
            if (buf == 0) phl0 ^= 1; else phl1 ^= 1;
        }
    }
}
#endif  // HAS_TC

// ---------------------------------------------------------------------------
// Generic GEMM with split-destination epilogue (8-warp epilogue: warps w and
// w+4 read the same TMEM subpartition (wid&3) and split the output groups).
//   cols 0..255   -> C0[r*ldc0 + c]       + bias0[c]
//   cols 256..511 -> C1[r*ldc1 + (c-256)] + bias1[c-256]   (NT==2 only)
// EPI 0: bias only.  EPI 2: fused gate — relu(D+bias) * relu(BN(A[r][c])).
// ---------------------------------------------------------------------------
template <int NT, int NC, int EPI>
__global__ void __launch_bounds__(256, 1)
tc_gemm_kernel(const float* __restrict__ A, const float* __restrict__ Wp,
               const float* __restrict__ bias0, const float* __restrict__ bias1,
               float* __restrict__ C0, int ldc0, float* __restrict__ C1, int ldc1,
               const float* __restrict__ mean, const float* __restrict__ rstd,
               const float* __restrict__ gamma, const float* __restrict__ beta)
{
    constexpr int NTOT = NT * 256;
    constexpr int K    = NC * 32;

#if HAS_TC
    extern __shared__ __align__(1024) char smem[];
    const uint32_t sb  = smem_u32(smem);
    const int      tid = threadIdx.x;
    const int      wid = tid >> 5, lane = tid & 31;
    const size_t   bm  = (size_t)blockIdx.x * 128;

    if (wid == 0) TCGEN05_ALLOC(sb, 512);
    if (tid == 0) {
        MBARRIER_INIT(sb + 8, 1);  MBARRIER_INIT(sb + 16, 1);
        MBARRIER_INIT(sb + 24, 1); MBARRIER_INIT(sb + 32, 1);
    }
    __syncthreads();
    uint32_t tb;
    asm volatile("ld.shared.b32 %0, [%1];" : "=r"(tb) : "r"(sb));

    int ph0 = 0, ph1 = 0;
    float rs_dummy = 0.f;
    tc_mainloop<NT, NC, false>(A, Wp, sb, tb, bm, ph0, ph1, &rs_dummy);

    MBARRIER_WAIT_PARITY(sb + 8,  ph0);
    MBARRIER_WAIT_PARITY(sb + 16, ph1);
    TCGEN05_FENCE_AFTER();

    // 8-warp epilogue: warp w covers groups [(w>>2)*NT*4, +NT*4)
    {
        const size_t row = bm + (size_t)(wid & 3) * 32 + lane;
        const int    g0  = (wid >> 2) * (NT * 4);
#pragma unroll
        for (int gi = 0; gi < NT * 4; gi++) {
            const int g = g0 + gi;
            uint32_t r[32];
            TCGEN05_LD_32X32B_X32(r, tb + g * 32);
            TCGEN05_WAIT_LD();
            const int c0g = g * 32;
            float* const base = (c0g < 256) ? (C0 + row * (size_t)ldc0 + c0g)
                                            : (C1 + row * (size_t)ldc1 + (c0g - 256));
            const float* const bb = (c0g < 256) ? (bias0 + c0g) : (bias1 + (c0g - 256));
#pragma unroll
            for (int j = 0; j < 32; j += 4) {
                float4 o;
                o.x = __uint_as_float(r[j + 0]) + bb[j + 0];
                o.y = __uint_as_float(r[j + 1]) + bb[j + 1];
                o.z = __uint_as_float(r[j + 2]) + bb[j + 2];
                o.w = __uint_as_float(r[j + 3]) + bb[j + 3];
                if (EPI == 2) {
                    const int c = c0g + j;
                    float4 x = *(const float4*)(A + row * (size_t)K + c);
                    o.x = fmaxf(o.x, 0.f) *
                          fmaxf(gamma[c+0]*(x.x-mean[c+0])*rstd[c+0]+beta[c+0], 0.f);
                    o.y = fmaxf(o.y, 0.f) *
                          fmaxf(gamma[c+1]*(x.y-mean[c+1])*rstd[c+1]+beta[c+1], 0.f);
                    o.z = fmaxf(o.z, 0.f) *
                          fmaxf(gamma[c+2]*(x.z-mean[c+2])*rstd[c+2]+beta[c+2], 0.f);
                    o.w = fmaxf(o.w, 0.f) *
                          fmaxf(gamma[c+3]*(x.w-mean[c+3])*rstd[c+3]+beta[c+3], 0.f);
                }
                *(float4*)(base + j) = o;
            }
        }
        TCGEN05_FENCE_BEFORE();
    }
    __syncthreads();
    if (wid == 0) { TCGEN05_RELINQ(); TCGEN05_DEALLOC(tb, 512); }

#else  // ----- generic fallback (correctness-only; never runs on sm_103a) ----
    const int    tid = threadIdx.x;
    const size_t bm  = (size_t)blockIdx.x * 128;
    for (int idx = tid; idx < 128 * NTOT; idx += 256) {
        const size_t row = bm + (idx / NTOT);
        const int    c   = idx % NTOT;
        float acc = (c < 256) ? bias0[c] : bias1[c - 256];
        for (int k = 0; k < K; k++)
            acc = fmaf(A[row * (size_t)K + k], w_packed(Wp, NTOT, c, k), acc);
        if (EPI == 2) {
            float x = A[row * (size_t)K + c];
            acc = fmaxf(acc, 0.f) * fmaxf(gamma[c]*(x-mean[c])*rstd[c]+beta[c], 0.f);
        }
        if (c < 256) C0[row * (size_t)ldc0 + c] = acc;
        else         C1[row * (size_t)ldc1 + (c - 256)] = acc;
    }
#endif
}

// ---------------------------------------------------------------------------
// Fused KV-projection + attention kernel.
// Epilogue now uses all 8 warps: warps w and w+4 share node (w&3) and split
// the 8 key groups (partial energies, combined in smem) and the 8 value
// groups (context).
// ---------------------------------------------------------------------------
__global__ void __launch_bounds__(256, 1)
kv_attn_kernel(const float* __restrict__ nbr, const float* __restrict__ Wp,
               const float* __restrict__ Q, const float* __restrict__ bk,
               const float* __restrict__ bv, float* __restrict__ ctx)
{
#if HAS_TC
    extern __shared__ __align__(1024) char smem[];
    const uint32_t sb  = smem_u32(smem);
    const int      tid = threadIdx.x;
    const int      wid = tid >> 5, lane = tid & 31;
    const size_t   bm  = (size_t)blockIdx.x * 128;

    if (wid == 0) TCGEN05_ALLOC(sb, 512);
    if (tid == 0) {
        MBARRIER_INIT(sb + 8, 1);  MBARRIER_INIT(sb + 16, 1);
        MBARRIER_INIT(sb + 24, 1); MBARRIER_INIT(sb + 32, 1);
    }
    __syncthreads();
    uint32_t tb;
    asm volatile("ld.shared.b32 %0, [%1];" : "=r"(tb) : "r"(sb));

    int ph0 = 0, ph1 = 0;
    float rs = 0.f;   // row-sum of this thread's A row (tid < 128: row bm+tid)
    tc_mainloop<2, 8, true>(nbr, Wp, sb, tb, bm, ph0, ph1, &rs);

    MBARRIER_WAIT_PARITY(sb + 8,  ph0);
    MBARRIER_WAIT_PARITY(sb + 16, ph1);
    TCGEN05_FENCE_AFTER();

    // Epilogue smem layout (bytes from dynamic smem base):
    //   1024 : qs[4][256]       (4 KB)
    //   5120 : bkq_s[4]
    //   5248 : e_part[8][32]    (1 KB)
    //   6272 : att_s[4][32]     (512 B)
    //   7168 : tr[8][32*33]     (33 KB)
    float* const qs_all  = (float*)(smem + 1024);
    float* const bkq_s   = (float*)(smem + 5120);
    float* const e_part  = (float*)(smem + 5248);
    float* const att_s   = (float*)(smem + 6272);
    float* const tr_all  = (float*)(smem + 7168);

    // Phase 0: warps 0-3 stage node's q and fold bk.q
    if (wid < 4) {
        const size_t node = (size_t)blockIdx.x * 4 + wid;
        float* qs = qs_all + wid * 256;
        float4 q0 = *(const float4*)(Q + node * 256 + lane * 8);
        float4 q1 = *(const float4*)(Q + node * 256 + lane * 8 + 4);
        *(float4*)(qs + lane * 8)     = q0;
        *(float4*)(qs + lane * 8 + 4) = q1;
        float4 b0 = *(const float4*)(bk + lane * 8);
        float4 b1 = *(const float4*)(bk + lane * 8 + 4);
        float bkq = q0.x*b0.x + q0.y*b0.y + q0.z*b0.z + q0.w*b0.w
                  + q1.x*b1.x + q1.y*b1.y + q1.z*b1.z + q1.w*b1.w;
#pragma unroll
        for (int o = 16; o; o >>= 1) bkq += __shfl_xor_sync(0xffffffffu, bkq, o);
        if (lane == 0) bkq_s[wid] = bkq;
    }
    __syncthreads();

    // Phase 1: all 8 warps — partial energies over 4 key groups each
    {
        const int    node = wid & 3;
        const int    gb   = (wid >> 2) * 4;
        const float* qs   = qs_all + node * 256;
        float e = 0.f;
#pragma unroll
        for (int i = 0; i < 4; i++) {
            uint32_t r[32];
            TCGEN05_LD_32X32B_X32(r, tb + (gb + i) * 32);
            TCGEN05_WAIT_LD();
            const float* qp = qs + (gb + i) * 32;
#pragma unroll
            for (int j = 0; j < 32; j++) e = fmaf(__uint_as_float(r[j]), qp[j], e);
        }
        e_part[wid * 32 + lane] = e;
    }
    __syncthreads();

    // Phase 2: warps 0-3 — combine, mask, softmax (rs valid: tid = w*32+lane < 128)
    if (wid < 4) {
        float e = e_part[wid * 32 + lane] + e_part[(wid + 4) * 32 + lane] + bkq_s[wid];
        if (rs == 0.0f) e = 1e-12f;
        float m = e;
#pragma unroll
        for (int o = 16; o; o >>= 1) m = fmaxf(m, __shfl_xor_sync(0xffffffffu, m, o));
        float ex = expf(e - m);
        float s = ex;
#pragma unroll
        for (int o = 16; o; o >>= 1) s += __shfl_xor_sync(0xffffffffu, s, o);
        att_s[wid * 32 + lane] = ex / s;
    }
    __syncthreads();

    // Phase 3: all 8 warps — context over 4 value groups each (smem transpose)
    {
        const int    node = wid & 3;
        const int    gb   = (wid >> 2) * 4;
        const float  a    = att_s[node * 32 + lane];
        float* const tr   = tr_all + wid * (32 * 33);
        const size_t nidx = (size_t)blockIdx.x * 4 + node;
#pragma unroll
        for (int i = 0; i < 4; i++) {
            const int g = gb + i;
            uint32_t r[32];
            TCGEN05_LD_32X32B_X32(r, tb + 256 + g * 32);
            TCGEN05_WAIT_LD();
#pragma unroll
            for (int j = 0; j < 32; j++) tr[j * 33 + lane] = __uint_as_float(r[j]) * a;
            __syncwarp();
            float c = bv[g * 32 + lane];
            const float* trow = tr + lane * 33;
#pragma unroll
            for (int k = 0; k < 32; k++) c += trow[k];
            ctx[nidx * 256 + g * 32 + lane] = c;
            __syncwarp();
        }
        TCGEN05_FENCE_BEFORE();
    }
    __syncthreads();
    if (wid == 0) { TCGEN05_RELINQ(); TCGEN05_DEALLOC(tb, 512); }

#else  // ----- generic fallback (correctness-only; never runs on sm_103a) ----
    const int    tid = threadIdx.x;
    const size_t bm  = (size_t)blockIdx.x * 128;
    __shared__ float att_f[128];

    if (tid < 128) {
        const size_t row  = bm + tid;
        const size_t node = row >> 5;
        float rsum = 0.f;
        for (int i = 0; i < DIN; i++) rsum += nbr[row * DIN + i];
        float e = 0.f;
        for (int d = 0; d < DOUT; d++) {
            float kd = bk[d];
            for (int i = 0; i < DIN; i++)
                kd = fmaf(nbr[row * DIN + i], w_packed(Wp, DCAT, d, i), kd);
            e = fmaf(kd, Q[node * DOUT + d], e);
        }
        if (rsum == 0.f) e = 1e-12f;
        float m = e;
        for (int o = 16; o; o >>= 1) m = fmaxf(m, __shfl_xor_sync(0xffffffffu, m, o));
        float ex = expf(e - m);
        float s = ex;
        for (int o = 16; o; o >>= 1) s += __shfl_xor_sync(0xffffffffu, s, o);
        att_f[tid] = ex / s;
    }
    __syncthreads();

    for (int idx = tid; idx < 4 * DOUT; idx += 256) {
        const int    ln   = idx >> 8;
        const int    d    = idx & 255;
        const size_t node = (size_t)blockIdx.x * 4 + ln;
        float c = bv[d];
        for (int k = 0; k < KNBR; k++) {
            const float* xr = nbr + (node * KNBR + k) * (size_t)DIN;
            float vd = 0.f;
            for (int i = 0; i < DIN; i++)
                vd = fmaf(xr[i], w_packed(Wp, DCAT, 256 + d, i), vd);
            c = fmaf(att_f[ln * 32 + k], vd, c);
        }
        ctx[node * DOUT + d] = c;
    }
#endif
}

// ---------------------------------------------------------------------------
// Weight packing: rows [0,256) from src0, rows [256, ntot) from src1;
// tf32-round into the chunk-major swizzled image. grid=(ntot/32, K/32).
// ---------------------------------------------------------------------------
__global__ void pack_w_kernel(const float* __restrict__ src0, const float* __restrict__ src1,
                              float* __restrict__ dst, int K, int ntot)
{
    const int c = blockIdx.y;
    const int r = blockIdx.x * 32 + (threadIdx.x >> 3);
    const int q = threadIdx.x & 7;
    const float* src = (r < 256) ? (src0 + (size_t)r * K) : (src1 + (size_t)(r - 256) * K);
    float4 v = *(const float4*)(src + c * 32 + q * 4);
    float4 o;
    o.x = __uint_as_float(rna_tf32(v.x));
    o.y = __uint_as_float(rna_tf32(v.y));
    o.z = __uint_as_float(rna_tf32(v.z));
    o.w = __uint_as_float(rna_tf32(v.w));
    *(float4*)(dst + (size_t)c * ((size_t)ntot * 32) +
               (sw128((uint32_t)(r * 128 + q * 16)) >> 2)) = o;
}

// ---------------------------------------------------------------------------
// BatchNorm statistics (deterministic two-phase)
// ---------------------------------------------------------------------------
__global__ void __launch_bounds__(256)
bn_partial_kernel(const float* __restrict__ ob, float* __restrict__ psum,
                  float* __restrict__ psq)
{
    const int b = blockIdx.x, t = threadIdx.x;   // 256 blocks x 64 rows
    float s0 = 0, s1 = 0, q0 = 0, q1 = 0;
    for (int r = 0; r < 64; r++) {
        const float* row = ob + ((size_t)b * 64 + r) * DCAT;
        float x0 = row[t], x1 = row[t + 256];
        s0 += x0; q0 += x0 * x0;
        s1 += x1; q1 += x1 * x1;
    }
    psum[b * DCAT + t]       = s0;
    psum[b * DCAT + t + 256] = s1;
    psq[b * DCAT + t]        = q0;
    psq[b * DCAT + t + 256]  = q1;
}

__global__ void bn_final_kernel(const float* __restrict__ psum, const float* __restrict__ psq,
                                float* __restrict__ mean, float* __restrict__ rstd)
{
    const int c = blockIdx.x * 256 + threadIdx.x;
    float s = 0, q = 0;
    for (int b = 0; b < 256; b++) { s += psum[b * DCAT + c]; q += psq[b * DCAT + c]; }
    float m = s / (float)N_NODES;
    float v = q / (float)N_NODES - m * m;
    mean[c] = m;
    rstd[c] = rsqrtf(v + 1e-5f);
}

// ---------------------------------------------------------------------------
// Launch
// ---------------------------------------------------------------------------
extern "C" void kernel_launch(void* const* d_in, const int* in_sizes, int n_in,
                              void* d_out, int out_size)
{
    const float* input = (const float*)d_in[0];
    const float* nbr   = (const float*)d_in[1];
    const float* Wq    = (const float*)d_in[2];
    const float* bq    = (const float*)d_in[3];
    const float* Wk    = (const float*)d_in[4];
    const float* bk    = (const float*)d_in[5];
    const float* Wv    = (const float*)d_in[6];
    const float* bv    = (const float*)d_in[7];
    const float* Wno   = (const float*)d_in[8];
    const float* bno   = (const float*)d_in[9];
    const float* Wio   = (const float*)d_in[10];
    const float* bio   = (const float*)d_in[11];
    const float* Wg    = (const float*)d_in[12];
    const float* bg    = (const float*)d_in[13];
    const float* gamma = (const float*)d_in[14];
    const float* beta  = (const float*)d_in[15];
    float* out = (float*)d_out;

    float *Qp, *ctxp, *obp, *Wqiop, *Wkvp, *Wnop, *Wgp;
    float *psump, *psqp, *meanp, *rstdp;
    cudaGetSymbolAddress((void**)&Qp,    g_Q);
    cudaGetSymbolAddress((void**)&ctxp,  g_ctx);
    cudaGetSymbolAddress((void**)&obp,   g_ob);
    cudaGetSymbolAddress((void**)&Wqiop, g_Wqio_pk);
    cudaGetSymbolAddress((void**)&Wkvp,  g_Wkv_pk);
    cudaGetSymbolAddress((void**)&Wnop,  g_Wno_pk);
    cudaGetSymbolAddress((void**)&Wgp,   g_Wg_pk);
    cudaGetSymbolAddress((void**)&psump, g_psum);
    cudaGetSymbolAddress((void**)&psqp,  g_psq);
    cudaGetSymbolAddress((void**)&meanp, g_mean);
    cudaGetSymbolAddress((void**)&rstdp, g_rstd);

    // Dynamic SMEM: 1024 header + 2 buffers of (128+NTOT)*128 bytes
    const int SMEM1 = 1024 + 2 * (128 + 256) * 128;   //  99328
    const int SMEM2 = 1024 + 2 * (128 + 512) * 128;   // 164864
    cudaFuncSetAttribute(tc_gemm_kernel<2, 8,  0>, cudaFuncAttributeMaxDynamicSharedMemorySize, SMEM2);
    cudaFuncSetAttribute(tc_gemm_kernel<1, 8,  0>, cudaFuncAttributeMaxDynamicSharedMemorySize, SMEM1);
    cudaFuncSetAttribute(tc_gemm_kernel<2, 16, 2>, cudaFuncAttributeMaxDynamicSharedMemorySize, SMEM2);
    cudaFuncSetAttribute(kv_attn_kernel,           cudaFuncAttributeMaxDynamicSharedMemorySize, SMEM2);

    // Pack weights into swizzled chunk-major images (tf32-rounded)
    pack_w_kernel<<<dim3(16, 8),  256>>>(Wq,  Wio,             Wqiop, DIN,  DCAT);
    pack_w_kernel<<<dim3(16, 8),  256>>>(Wk,  Wv,              Wkvp,  DIN,  DCAT);
    pack_w_kernel<<<dim3(8,  8),  256>>>(Wno, Wno,             Wnop,  DOUT, DOUT);
    pack_w_kernel<<<dim3(16, 16), 256>>>(Wg,  Wg + 256 * DCAT, Wgp,   DCAT, DCAT);

    // fused Q + self projections: [queries | self_out] = input @ [Wq;Wio]^T
    tc_gemm_kernel<2, 8, 0><<<N_NODES / 128, 256, SMEM2>>>(
        input, Wqiop, bq, bio, Qp, DOUT, obp, DCAT,
        nullptr, nullptr, nullptr, nullptr);

    // fused: keys|values projection + masked softmax attention -> context
    kv_attn_kernel<<<NROWS / 128, 256, SMEM2>>>(nbr, Wkvp, Qp, bk, bv, ctxp);

    // neigh_out = context @ Wno^T + bno -> output[:, 256:512]
    tc_gemm_kernel<1, 8, 0><<<N_NODES / 128, 256, SMEM1>>>(
        ctxp, Wnop, bno, bno, obp + 256, DCAT, nullptr, 0,
        nullptr, nullptr, nullptr, nullptr);

    // BatchNorm statistics (needed before fused gate epilogue)
    bn_partial_kernel<<<256, 256>>>(obp, psump, psqp);
    bn_final_kernel<<<2, 256>>>(psump, psqp, meanp, rstdp);

    // gate GEMM with fused epilogue: out = relu(ob@Wg^T+bg) * relu(BN(ob))
    tc_gemm_kernel<2, 16, 2><<<N_NODES / 128, 256, SMEM2>>>(
        obp, Wgp, bg, bg + 256, out, DCAT, out + 256, DCAT,
        meanp, rstdp, gamma, beta);
}